// round 6
// baseline (speedup 1.0000x reference)
#include <cuda_runtime.h>
#include <cuda_bf16.h>
#include <cstdint>

#define N_TOK 2048
#define DIM   32
#define RFEAT 64
#define HDIM  128
#define TJ    64
#define NTILES (N_TOK / TJ)

// ---------- scratch (device globals; no allocation allowed) ----------
__device__ __align__(16) float    g_Q[N_TOK * DIM];
__device__ __align__(16) float    g_V[N_TOK * DIM];
__device__ __align__(16) float    g_KTf[DIM * N_TOK];            // [k][j] fp32, * log2e/sqrt(d)
__device__ __align__(16) float    g_VTf[DIM * N_TOK];            // [c][j] fp32
__device__ __align__(16) float    g_phiQ[N_TOK * RFEAT];
__device__ __align__(16) float    g_phiK[N_TOK * RFEAT];         // fp32, for k2
__device__ __align__(16) unsigned g_PKT2[(RFEAT / 2) * N_TOK];   // [r2][j] bf16x2 r-pairs
__device__ __align__(16) float    g_M[RFEAT * DIM];              // phi_K^T @ V

__device__ __forceinline__ float fast_ex2(float x) {
    float y;
    asm("ex2.approx.ftz.f32 %0, %1;" : "=f"(y) : "f"(x));
    return y;
}
__device__ __forceinline__ float warp_sum(float v) {
    v += __shfl_xor_sync(0xffffffffu, v, 16);
    v += __shfl_xor_sync(0xffffffffu, v, 8);
    v += __shfl_xor_sync(0xffffffffu, v, 4);
    v += __shfl_xor_sync(0xffffffffu, v, 2);
    v += __shfl_xor_sync(0xffffffffu, v, 1);
    return v;
}
__device__ __forceinline__ __nv_bfloat162 u2bf(unsigned u) {
    return *reinterpret_cast<__nv_bfloat162*>(&u);
}
__device__ __forceinline__ unsigned packbf(float a, float b) {
    __nv_bfloat162 h = __floats2bfloat162_rn(a, b);
    return *reinterpret_cast<unsigned*>(&h);
}
// packed f32x2 FMA (Blackwell FFMA2): acc = a*b + acc  (lane-wise on 2 packed f32)
__device__ __forceinline__ void fma2(unsigned long long& acc,
                                     unsigned long long a, unsigned long long b) {
    asm("fma.rn.f32x2 %0, %1, %2, %3;" : "=l"(acc) : "l"(a), "l"(b), "l"(acc));
}
__device__ __forceinline__ float unpack_sum(unsigned long long p) {
    unsigned lo, hi;
    asm("mov.b64 {%0, %1}, %2;" : "=r"(lo), "=r"(hi) : "l"(p));
    return __uint_as_float(lo) + __uint_as_float(hi);
}

#define CP_ASYNC16(dst_s, src_g) \
    asm volatile("cp.async.cg.shared.global [%0], [%1], 16;" :: "r"(dst_s), "l"(src_g))
#define CP_COMMIT() asm volatile("cp.async.commit_group;")
#define CP_WAIT0()  asm volatile("cp.async.wait_group 0;" ::: "memory")

#define L2E    1.4426950408889634f
#define KSCALE ((float)(1.4426950408889634 / 5.6568542494923806)) // log2e/sqrt(32)

// ---------------------------------------------------------------------
// K1: warp-per-row QKV + norms + random features. 4 rows/block, 512
// blocks -> deep latency hiding. Packs transposed fp32 K/V operands.
// ---------------------------------------------------------------------
__global__ void __launch_bounds__(128) k1_proj(const float* __restrict__ Z,
                        const float* __restrict__ Wq, const float* __restrict__ bq,
                        const float* __restrict__ Wk, const float* __restrict__ bk,
                        const float* __restrict__ Wv, const float* __restrict__ bv,
                        const float* __restrict__ omega)
{
    __shared__ float sW[3][DIM * DIM];
    __shared__ float sB[3][DIM];
    __shared__ float sOm[DIM * RFEAT];
    __shared__ float sRow[4][DIM];
    __shared__ float sAn[4][DIM];
    __shared__ float sK[4][33];
    __shared__ float sVv[4][33];

    int tid = threadIdx.x, lane = tid & 31, w = tid >> 5;
    for (int idx = tid; idx < DIM * DIM; idx += 128) {
        sW[0][idx] = Wq[idx]; sW[1][idx] = Wk[idx]; sW[2][idx] = Wv[idx];
    }
    for (int idx = tid; idx < DIM * RFEAT; idx += 128) sOm[idx] = omega[idx];
    if (tid < DIM) { sB[0][tid] = bq[tid]; sB[1][tid] = bk[tid]; sB[2][tid] = bv[tid]; }

    int i0 = blockIdx.x * 4;
    int i = i0 + w;
    float zk = Z[i * DIM + lane];
    __syncthreads();

    sRow[w][lane] = zk;
    __syncwarp();

    float a[3];
    #pragma unroll
    for (int p = 0; p < 3; p++) {
        float s0 = sB[p][lane], s1 = 0.f;
        #pragma unroll
        for (int k = 0; k < DIM; k += 2) {
            s0 = fmaf(sRow[w][k],     sW[p][k * DIM + lane],       s0);
            s1 = fmaf(sRow[w][k + 1], sW[p][(k + 1) * DIM + lane], s1);
        }
        a[p] = s0 + s1;
    }
    g_Q[i * DIM + lane] = a[0];
    g_V[i * DIM + lane] = a[2];
    sK[w][lane]  = a[1] * KSCALE;
    sVv[w][lane] = a[2];

    #pragma unroll
    for (int p = 0; p < 2; p++) {
        float v = a[p];
        float ss = warp_sum(v * v);
        float an = v * (1.f / fmaxf(sqrtf(ss), 1e-6f));
        sAn[w][lane] = an;
        __syncwarp();
        float d0 = 0.f, d1 = 0.f, d2 = 0.f, d3 = 0.f;
        #pragma unroll
        for (int k = 0; k < DIM; k += 2) {
            float ab0 = sAn[w][k], ab1 = sAn[w][k + 1];
            float2 om0 = *(const float2*)&sOm[k * RFEAT + 2 * lane];
            float2 om1 = *(const float2*)&sOm[(k + 1) * RFEAT + 2 * lane];
            d0 = fmaf(ab0, om0.x, d0); d1 = fmaf(ab0, om0.y, d1);
            d2 = fmaf(ab1, om1.x, d2); d3 = fmaf(ab1, om1.y, d3);
        }
        float e0 = fast_ex2((d0 + d2) * L2E) * 0.125f;  // exp(d)/sqrt(r), r=64
        float e1 = fast_ex2((d1 + d3) * L2E) * 0.125f;
        float2 ph; ph.x = e0; ph.y = e1;
        if (p == 0) {
            *(float2*)&g_phiQ[i * RFEAT + 2 * lane] = ph;
        } else {
            *(float2*)&g_phiK[i * RFEAT + 2 * lane] = ph;
            g_PKT2[lane * N_TOK + i] = packbf(e0, e1);   // [r2=lane][j=i]
        }
        __syncwarp();
    }

    __syncthreads();
    // pack phase: transposed fp32 j-pairs for this block's 4 rows
    if (tid < 64) {
        int k = tid >> 1, p = tid & 1;
        int dst = k * N_TOK + i0 + 2 * p;
        *(float2*)&g_KTf[dst] = make_float2(sK[2 * p][k],  sK[2 * p + 1][k]);
        *(float2*)&g_VTf[dst] = make_float2(sVv[2 * p][k], sVv[2 * p + 1][k]);
    }
}

// ---------------------------------------------------------------------
// K2: M = phi_K^T @ V   [64 x 32]. One block per r.
// ---------------------------------------------------------------------
__global__ void k2_kv()
{
    int r = blockIdx.x;
    int tid = threadIdx.x, lane = tid & 31, w = tid >> 5;

    float acc[DIM];
    #pragma unroll
    for (int c = 0; c < DIM; c++) acc[c] = 0.f;

    for (int n = tid; n < N_TOK; n += 256) {
        float pk = g_phiK[n * RFEAT + r];
        const float4* v4 = reinterpret_cast<const float4*>(g_V + n * DIM);
        #pragma unroll
        for (int c4 = 0; c4 < DIM / 4; c4++) {
            float4 t = v4[c4];
            acc[c4 * 4 + 0] = fmaf(pk, t.x, acc[c4 * 4 + 0]);
            acc[c4 * 4 + 1] = fmaf(pk, t.y, acc[c4 * 4 + 1]);
            acc[c4 * 4 + 2] = fmaf(pk, t.z, acc[c4 * 4 + 2]);
            acc[c4 * 4 + 3] = fmaf(pk, t.w, acc[c4 * 4 + 3]);
        }
    }

    __shared__ float sm[8][DIM];
    float mine = 0.f;
    #pragma unroll
    for (int c = 0; c < DIM; c++) {
        float s = warp_sum(acc[c]);
        if (lane == c) mine = s;
    }
    sm[w][lane] = mine;
    __syncthreads();
    if (tid < DIM) {
        float t = 0.f;
        #pragma unroll
        for (int ww = 0; ww < 8; ww++) t += sm[ww][tid];
        g_M[r * DIM + tid] = t;
    }
}

// ---------------------------------------------------------------------
// K3: attention + fused Wo/LN1/FFN/LN2. 512 threads, 16 rows/block.
// Thread owns j-pair. exp: fp32 v2 loads (no unpack). AV: FFMA2 packed.
// Dynamic smem layout (byte offsets):
//   0      sKTf [2][32][64]  f32  16384
//   16384  sPK2 [2][32][64]  u32  16384
//   32768  sVTf [2][32][68]  f32  17408 (row stride 68 floats, pad)
//   50176  sS   [16][64]     f32   4096
//   54272  sPQ  [16][64]     f32   4096
//   58368  sM   [64][32]     f32   8192
//   66560  sWo  [32][32]     f32   4096
//   70656  sW1  [32][128]    f32  16384
//   87040  sW2  [128][32]    f32  16384
//   103424 sH   [16][128]    f32   8192
//   111616 sA   [16][32]     f32   2048
//   113664 sZ1  [16][32]     f32   2048
//   115712 sb1  [128]        f32    512
//   116224 sVec [6][32]      f32    768
//   total 116992
// ---------------------------------------------------------------------
#define K3_SMEM_BYTES 116992

__device__ __forceinline__ void k3_stage_tile(int t, int b, int tid, unsigned smem_base)
{
    int tj = t * TJ;
    int row = tid >> 4, c16 = tid & 15;
    // KT fp32 tile: 32 rows x 256B
    unsigned d0 = smem_base + (unsigned)(b * 8192 + row * 256 + c16 * 16);
    CP_ASYNC16(d0, g_KTf + row * N_TOK + tj + c16 * 4);
    // PK bf16x2 tile: 32 rows x 256B
    unsigned d1 = smem_base + (unsigned)(16384 + b * 8192 + row * 256 + c16 * 16);
    CP_ASYNC16(d1, g_PKT2 + row * N_TOK + tj + c16 * 4);
    // VT fp32 tile: 32 rows x 256B data, row stride 272B
    unsigned d2 = smem_base + (unsigned)(32768 + b * 8704 + row * 272 + c16 * 16);
    CP_ASYNC16(d2, g_VTf + row * N_TOK + tj + c16 * 4);
}

__global__ void __launch_bounds__(512, 1) k3_attn(
    const int* __restrict__ mask,
    const float* __restrict__ Wo, const float* __restrict__ bo,
    const float* __restrict__ Z,
    const float* __restrict__ W1, const float* __restrict__ b1,
    const float* __restrict__ W2, const float* __restrict__ b2,
    const float* __restrict__ g1, const float* __restrict__ be1,
    const float* __restrict__ g2, const float* __restrict__ be2,
    float* __restrict__ out)
{
    extern __shared__ char sm_raw[];
    unsigned smem_base = (unsigned)__cvta_generic_to_shared(sm_raw);
    float*    sS    = (float*)(sm_raw + 50176);
    float*    sPQ   = (float*)(sm_raw + 54272);
    float*    sM    = (float*)(sm_raw + 58368);
    float*    sWo   = (float*)(sm_raw + 66560);
    float*    sW1   = (float*)(sm_raw + 70656);
    float*    sW2   = (float*)(sm_raw + 87040);
    float*    sH    = (float*)(sm_raw + 103424);
    float*    sA    = (float*)(sm_raw + 111616);
    float*    sZ1   = (float*)(sm_raw + 113664);
    float*    sb1   = (float*)(sm_raw + 115712);
    float*    sVec  = (float*)(sm_raw + 116224);

    int tid = threadIdx.x, lane = tid & 31, w = tid >> 5;

    // stage constants
    for (int idx = tid; idx < RFEAT * DIM; idx += 512) sM[idx] = g_M[idx];
    for (int idx = tid; idx < DIM * DIM; idx += 512) sWo[idx] = Wo[idx];
    for (int idx = tid; idx < DIM * HDIM; idx += 512) { sW1[idx] = W1[idx]; sW2[idx] = W2[idx]; }
    if (tid < HDIM) sb1[tid] = b1[tid];
    if (tid < DIM) {
        sVec[tid] = bo[tid];        sVec[32 + tid] = b2[tid];
        sVec[64 + tid] = g1[tid];   sVec[96 + tid] = be1[tid];
        sVec[128 + tid] = g2[tid];  sVec[160 + tid] = be2[tid];
    }

    int i = blockIdx.x * 16 + w;

    float q[DIM];
    #pragma unroll
    for (int k4 = 0; k4 < DIM / 4; k4++) {
        float4 t = *(const float4*)(g_Q + i * DIM + k4 * 4);
        q[k4 * 4 + 0] = t.x; q[k4 * 4 + 1] = t.y; q[k4 * 4 + 2] = t.z; q[k4 * 4 + 3] = t.w;
    }
    unsigned pq2[RFEAT / 2];
    #pragma unroll
    for (int r4 = 0; r4 < RFEAT / 4; r4++) {
        float4 t = *(const float4*)(g_phiQ + i * RFEAT + r4 * 4);
        pq2[2 * r4]     = packbf(t.x, t.y);
        pq2[2 * r4 + 1] = packbf(t.z, t.w);
    }
    *(float2*)&sPQ[w * RFEAT + 2 * lane] = *(const float2*)(g_phiQ + i * RFEAT + 2 * lane);
    float zres = Z[i * DIM + lane];

    const int2* mrow2 = (const int2*)(mask + (size_t)i * N_TOK);
    int2 mv = mrow2[lane];
    unsigned long long accp0 = 0ull, accp1 = 0ull;

    k3_stage_tile(0, 0, tid, smem_base);
    CP_COMMIT();

    for (int t = 0; t < NTILES; t++) {
        CP_WAIT0();
        __syncthreads();
        if (t + 1 < NTILES) { k3_stage_tile(t + 1, (t + 1) & 1, tid, smem_base); CP_COMMIT(); }

        int b = t & 1;
        const float2* KT = (const float2*)(sm_raw + b * 8192);
        const uint2*  PK = (const uint2*)(sm_raw + 16384 + b * 8192);
        const float*  vrow = (const float*)(sm_raw + 32768 + b * 8704) + lane * 68;

        int2 nmv = make_int2(0, 0);
        if (t + 1 < NTILES) nmv = mrow2[(t + 1) * 32 + lane];

        // ---- exp part: fp32 j-pair loads, no unpack ----
        float eA0 = 0.f, eA1 = 0.f, eB0 = 0.f, eB1 = 0.f;
        #pragma unroll
        for (int k = 0; k < DIM; k += 2) {
            float2 a0 = KT[k * 32 + lane];
            float2 a1 = KT[(k + 1) * 32 + lane];
            eA0 += fast_ex2(q[k]     * a0.x);
            eB0 += fast_ex2(q[k]     * a0.y);
            eA1 += fast_ex2(q[k + 1] * a1.x);
            eB1 += fast_ex2(q[k + 1] * a1.y);
        }

        // ---- phi part: HFMA2 bf16x2 ----
        __nv_bfloat162 pA0 = __floats2bfloat162_rn(0.f, 0.f);
        __nv_bfloat162 pA1 = pA0, pB0 = pA0, pB1 = pA0;
        #pragma unroll
        for (int r2 = 0; r2 < RFEAT / 2; r2 += 2) {
            uint2 k0 = PK[r2 * 32 + lane];
            uint2 k1 = PK[(r2 + 1) * 32 + lane];
            pA0 = __hfma2(u2bf(pq2[r2]),     u2bf(k0.x), pA0);
            pB0 = __hfma2(u2bf(pq2[r2]),     u2bf(k0.y), pB0);
            pA1 = __hfma2(u2bf(pq2[r2 + 1]), u2bf(k1.x), pA1);
            pB1 = __hfma2(u2bf(pq2[r2 + 1]), u2bf(k1.y), pB1);
        }
        float2 fa0 = __bfloat1622float2(pA0), fa1 = __bfloat1622float2(pA1);
        float2 fb0 = __bfloat1622float2(pB0), fb1 = __bfloat1622float2(pB1);
        float phiA = (fa0.x + fa0.y) + (fa1.x + fa1.y);
        float phiB = (fb0.x + fb0.y) + (fb1.x + fb1.y);

        float2 sv;
        sv.x = (mv.x == 0) ? (((eA0 + eA1) + (eB0 - eB0)) - phiA) : 0.f;
        sv.x = (mv.x == 0) ? (((eA0 + eA1)) - phiA) : 0.f;
        sv.y = (mv.y == 0) ? (((eB0 + eB1)) - phiB) : 0.f;
        *(float2*)&sS[w * TJ + 2 * lane] = sv;
        __syncwarp();

        // ---- AV: packed FFMA2, lane = output column c ----
        const ulonglong2* VR = (const ulonglong2*)vrow;
        const ulonglong2* SR = (const ulonglong2*)&sS[w * TJ];
        #pragma unroll
        for (int u = 0; u < 16; u++) {
            ulonglong2 vv = VR[u];
            ulonglong2 ss = SR[u];
            fma2(accp0, ss.x, vv.x);
            fma2(accp1, ss.y, vv.y);
        }
        mv = nmv;
        __syncwarp();
    }

    // ---- epilogue: + low-rank, normalize, @Wo+bo, LN1, FFN, LN2 ----
    float lr = 0.f;
    #pragma unroll
    for (int r = 0; r < RFEAT; r++) lr = fmaf(sPQ[w * RFEAT + r], sM[r * DIM + lane], lr);

    float attn = (unpack_sum(accp0) + unpack_sum(accp1)) + lr;
    float denom = fmaxf(warp_sum(attn), 1e-6f);
    float a = attn / denom;

    sA[w * DIM + lane] = a;
    __syncwarp();
    float o = sVec[lane];   // bo
    #pragma unroll
    for (int c = 0; c < DIM; c++) o = fmaf(sA[w * DIM + c], sWo[c * DIM + lane], o);

    // LN1
    float x = zres + o;
    float mu = warp_sum(x) * (1.f / 32.f);
    float dd = x - mu;
    float var = warp_sum(dd * dd) * (1.f / 32.f);
    float z1 = dd * rsqrtf(var + 1e-5f) * sVec[64 + lane] + sVec[96 + lane];
    sZ1[w * DIM + lane] = z1;
    __syncwarp();

    // FFN up + relu
    float h[4];
    #pragma unroll
    for (int u = 0; u < 4; u++) h[u] = sb1[lane + u * 32];
    #pragma unroll
    for (int k = 0; k < DIM; k++) {
        float zk = sZ1[w * DIM + k];
        #pragma unroll
        for (int u = 0; u < 4; u++) h[u] = fmaf(zk, sW1[k * HDIM + lane + u * 32], h[u]);
    }
    #pragma unroll
    for (int u = 0; u < 4; u++) sH[w * HDIM + lane + u * 32] = fmaxf(h[u], 0.f);
    __syncwarp();

    // FFN down
    float o0 = sVec[32 + lane], o1 = 0.f, o2 = 0.f, o3 = 0.f;
    #pragma unroll
    for (int j = 0; j < HDIM; j += 4) {
        o0 = fmaf(sH[w * HDIM + j + 0], sW2[(j + 0) * DIM + lane], o0);
        o1 = fmaf(sH[w * HDIM + j + 1], sW2[(j + 1) * DIM + lane], o1);
        o2 = fmaf(sH[w * HDIM + j + 2], sW2[(j + 2) * DIM + lane], o2);
        o3 = fmaf(sH[w * HDIM + j + 3], sW2[(j + 3) * DIM + lane], o3);
    }
    float y = z1 + ((o0 + o1) + (o2 + o3));

    // LN2
    float mu2 = warp_sum(y) * (1.f / 32.f);
    float dd2 = y - mu2;
    float var2 = warp_sum(dd2 * dd2) * (1.f / 32.f);
    out[i * DIM + lane] = dd2 * rsqrtf(var2 + 1e-5f) * sVec[128 + lane] + sVec[160 + lane];
}

// ---------------------------------------------------------------------
extern "C" void kernel_launch(void* const* d_in, const int* in_sizes, int n_in,
                              void* d_out, int out_size)
{
    const float* Z    = (const float*)d_in[0];
    const int*   mask = (const int*)  d_in[1];
    const float* Wq = (const float*)d_in[2],  *bq = (const float*)d_in[3];
    const float* Wk = (const float*)d_in[4],  *bk = (const float*)d_in[5];
    const float* Wv = (const float*)d_in[6],  *bv = (const float*)d_in[7];
    const float* Wo = (const float*)d_in[8],  *bo = (const float*)d_in[9];
    const float* W1 = (const float*)d_in[10], *b1 = (const float*)d_in[11];
    const float* W2 = (const float*)d_in[12], *b2 = (const float*)d_in[13];
    const float* g1 = (const float*)d_in[14], *be1 = (const float*)d_in[15];
    const float* g2 = (const float*)d_in[16], *be2 = (const float*)d_in[17];
    const float* omega = (const float*)d_in[18];

    cudaFuncSetAttribute(k3_attn, cudaFuncAttributeMaxDynamicSharedMemorySize, K3_SMEM_BYTES);

    k1_proj<<<N_TOK / 4, 128>>>(Z, Wq, bq, Wk, bk, Wv, bv, omega);
    k2_kv<<<RFEAT, 256>>>();
    k3_attn<<<N_TOK / 16, 512, K3_SMEM_BYTES>>>(mask, Wo, bo, Z,
                                                W1, b1, W2, b2,
                                                g1, be1, g2, be2, (float*)d_out);
}

// round 8
// speedup vs baseline: 1.1034x; 1.1034x over previous
#include <cuda_runtime.h>
#include <cuda_bf16.h>
#include <cstdint>

#define N_TOK 2048
#define DIM   32
#define RFEAT 64
#define HDIM  128
#define TJ    64
#define NTILES (N_TOK / TJ)

// ---------- scratch (device globals; no allocation allowed) ----------
__device__ __align__(16) float    g_Q[N_TOK * DIM];
__device__ __align__(16) float    g_V[N_TOK * DIM];
__device__ __align__(16) float    g_phiQ[N_TOK * RFEAT];
__device__ __align__(16) float    g_phiK[N_TOK * RFEAT];         // fp32, for k2
__device__ __align__(16) unsigned g_phiQh2[N_TOK * (RFEAT / 2)]; // row-major bf16x2 r-pairs
__device__ __align__(16) unsigned g_phiKh2[N_TOK * (RFEAT / 2)];
__device__ __align__(16) unsigned g_KT2[DIM * (N_TOK / 2)];      // [k][j2] bf16x2 j-pairs (scaled K)
__device__ __align__(16) unsigned g_VT2[DIM * (N_TOK / 2)];      // [c][j2] bf16x2 j-pairs
__device__ __align__(16) float    g_M[RFEAT * DIM];              // phi_K^T @ V
__device__ __align__(16) float    g_P[N_TOK * N_TOK];            // phiQ @ phiK^T (16MB)

__device__ __forceinline__ float fast_ex2(float x) {
    float y;
    asm("ex2.approx.ftz.f32 %0, %1;" : "=f"(y) : "f"(x));
    return y;
}
__device__ __forceinline__ float warp_sum(float v) {
    v += __shfl_xor_sync(0xffffffffu, v, 16);
    v += __shfl_xor_sync(0xffffffffu, v, 8);
    v += __shfl_xor_sync(0xffffffffu, v, 4);
    v += __shfl_xor_sync(0xffffffffu, v, 2);
    v += __shfl_xor_sync(0xffffffffu, v, 1);
    return v;
}
__device__ __forceinline__ unsigned packbf(float a, float b) {
    __nv_bfloat162 h = __floats2bfloat162_rn(a, b);
    return *reinterpret_cast<unsigned*>(&h);
}
#define BFLO(u) __uint_as_float((u) << 16)
#define BFHI(u) __uint_as_float((u) & 0xffff0000u)

#define CP_ASYNC16(dst_s, src_g) \
    asm volatile("cp.async.cg.shared.global [%0], [%1], 16;" :: "r"(dst_s), "l"(src_g))
#define CP_COMMIT() asm volatile("cp.async.commit_group;")
#define CP_WAIT0()  asm volatile("cp.async.wait_group 0;" ::: "memory")

#define L2E    1.4426950408889634f
#define KSCALE ((float)(1.4426950408889634 / 5.6568542494923806)) // log2e/sqrt(32)

// ---------------------------------------------------------------------
// K1: warp-per-row QKV + norms + random features (R5-proven version).
// Emits bf16x2 transposed K/V j-pairs and row-major bf16x2 phi for kP.
// ---------------------------------------------------------------------
__global__ void __launch_bounds__(512) k1_proj(const float* __restrict__ Z,
                        const float* __restrict__ Wq, const float* __restrict__ bq,
                        const float* __restrict__ Wk, const float* __restrict__ bk,
                        const float* __restrict__ Wv, const float* __restrict__ bv,
                        const float* __restrict__ omega)
{
    __shared__ float sW[3][DIM * DIM];
    __shared__ float sB[3][DIM];
    __shared__ float sOm[DIM * RFEAT];
    __shared__ float sRow[16][DIM];
    __shared__ float sAn[16][DIM];
    __shared__ float sK[16][33];
    __shared__ float sVv[16][33];

    int tid = threadIdx.x, lane = tid & 31, w = tid >> 5;
    for (int idx = tid; idx < DIM * DIM; idx += 512) {
        sW[0][idx] = Wq[idx]; sW[1][idx] = Wk[idx]; sW[2][idx] = Wv[idx];
    }
    for (int idx = tid; idx < DIM * RFEAT; idx += 512) sOm[idx] = omega[idx];
    if (tid < DIM) { sB[0][tid] = bq[tid]; sB[1][tid] = bk[tid]; sB[2][tid] = bv[tid]; }

    int i0 = blockIdx.x * 16;
    int i = i0 + w;
    float zk = Z[i * DIM + lane];
    __syncthreads();

    sRow[w][lane] = zk;
    __syncwarp();

    float a[3];
    #pragma unroll
    for (int p = 0; p < 3; p++) {
        float s0 = sB[p][lane], s1 = 0.f;
        #pragma unroll
        for (int k = 0; k < DIM; k += 2) {
            s0 = fmaf(sRow[w][k],     sW[p][k * DIM + lane],       s0);
            s1 = fmaf(sRow[w][k + 1], sW[p][(k + 1) * DIM + lane], s1);
        }
        a[p] = s0 + s1;
    }
    g_Q[i * DIM + lane] = a[0];
    g_V[i * DIM + lane] = a[2];
    sK[w][lane]  = a[1] * KSCALE;
    sVv[w][lane] = a[2];

    #pragma unroll
    for (int p = 0; p < 2; p++) {
        float v = a[p];
        float ss = warp_sum(v * v);
        float an = v * (1.f / fmaxf(sqrtf(ss), 1e-6f));
        sAn[w][lane] = an;
        __syncwarp();
        float d0 = 0.f, d1 = 0.f, d2 = 0.f, d3 = 0.f;
        #pragma unroll
        for (int k = 0; k < DIM; k += 2) {
            float ab0 = sAn[w][k], ab1 = sAn[w][k + 1];
            float2 om0 = *(const float2*)&sOm[k * RFEAT + 2 * lane];
            float2 om1 = *(const float2*)&sOm[(k + 1) * RFEAT + 2 * lane];
            d0 = fmaf(ab0, om0.x, d0); d1 = fmaf(ab0, om0.y, d1);
            d2 = fmaf(ab1, om1.x, d2); d3 = fmaf(ab1, om1.y, d3);
        }
        float e0 = fast_ex2((d0 + d2) * L2E) * 0.125f;  // exp(d)/sqrt(r), r=64
        float e1 = fast_ex2((d1 + d3) * L2E) * 0.125f;
        float2 ph; ph.x = e0; ph.y = e1;
        if (p == 0) {
            *(float2*)&g_phiQ[i * RFEAT + 2 * lane] = ph;
            g_phiQh2[i * (RFEAT / 2) + lane] = packbf(e0, e1);
        } else {
            *(float2*)&g_phiK[i * RFEAT + 2 * lane] = ph;
            g_phiKh2[i * (RFEAT / 2) + lane] = packbf(e0, e1);
        }
        __syncwarp();
    }

    __syncthreads();
    // pack phase: transposed bf16x2 j-pairs for this block's 16 rows
    if (tid < 256) {
        int k = tid >> 3, p = tid & 7;
        int dst = k * (N_TOK / 2) + (i0 >> 1) + p;
        g_KT2[dst] = packbf(sK[2 * p][k],  sK[2 * p + 1][k]);
        g_VT2[dst] = packbf(sVv[2 * p][k], sVv[2 * p + 1][k]);
    }
}

// ---------------------------------------------------------------------
// kP: P = phiQ @ phiK^T via warp-level mma.sync bf16 (fp32 accum).
// Fragment words ARE the packed g_phi*h2 u32s — direct LDG, no ldmatrix.
// Warp tile: 16 (i) x 64 (j). Block: 8 warps = 128 x 64. Grid (16, 32).
// ---------------------------------------------------------------------
__global__ void __launch_bounds__(256) kP_phigemm()
{
    int tid = threadIdx.x, lane = tid & 31, wi = tid >> 5;
    int g   = lane >> 2;      // group id 0..7
    int tig = lane & 3;       // thread in group 0..3
    int ib  = blockIdx.x * 128 + wi * 16;   // warp's i-tile base
    int j0  = blockIdx.y * 64;              // block's j-tile base

    float d[8][4];
    #pragma unroll
    for (int nc = 0; nc < 8; nc++)
        #pragma unroll
        for (int u = 0; u < 4; u++) d[nc][u] = 0.f;

    #pragma unroll
    for (int ks = 0; ks < 4; ks++) {        // K = 64 in 4 steps of 16
        int kp = ks * 8 + tig;              // r-pair index
        unsigned a0 = g_phiQh2[(ib + g)     * 32 + kp];
        unsigned a1 = g_phiQh2[(ib + g + 8) * 32 + kp];
        unsigned a2 = g_phiQh2[(ib + g)     * 32 + kp + 4];
        unsigned a3 = g_phiQh2[(ib + g + 8) * 32 + kp + 4];
        #pragma unroll
        for (int nc = 0; nc < 8; nc++) {
            int jn = j0 + nc * 8 + g;
            unsigned b0 = g_phiKh2[jn * 32 + kp];
            unsigned b1 = g_phiKh2[jn * 32 + kp + 4];
            asm volatile(
                "mma.sync.aligned.m16n8k16.row.col.f32.bf16.bf16.f32 "
                "{%0,%1,%2,%3}, {%4,%5,%6,%7}, {%8,%9}, {%0,%1,%2,%3};"
                : "+f"(d[nc][0]), "+f"(d[nc][1]), "+f"(d[nc][2]), "+f"(d[nc][3])
                : "r"(a0), "r"(a1), "r"(a2), "r"(a3), "r"(b0), "r"(b1));
        }
    }

    // store: d0,d1 -> row g, cols tig*2,+1 ; d2,d3 -> row g+8
    #pragma unroll
    for (int nc = 0; nc < 8; nc++) {
        int jc = j0 + nc * 8 + tig * 2;
        *(float2*)(g_P + (size_t)(ib + g)     * N_TOK + jc) = make_float2(d[nc][0], d[nc][1]);
        *(float2*)(g_P + (size_t)(ib + g + 8) * N_TOK + jc) = make_float2(d[nc][2], d[nc][3]);
    }
}

// ---------------------------------------------------------------------
// K2: M = phi_K^T @ V   [64 x 32]. One block per r.
// ---------------------------------------------------------------------
__global__ void k2_kv()
{
    int r = blockIdx.x;
    int tid = threadIdx.x, lane = tid & 31, w = tid >> 5;

    float acc[DIM];
    #pragma unroll
    for (int c = 0; c < DIM; c++) acc[c] = 0.f;

    for (int n = tid; n < N_TOK; n += 256) {
        float pk = g_phiK[n * RFEAT + r];
        const float4* v4 = reinterpret_cast<const float4*>(g_V + n * DIM);
        #pragma unroll
        for (int c4 = 0; c4 < DIM / 4; c4++) {
            float4 t = v4[c4];
            acc[c4 * 4 + 0] = fmaf(pk, t.x, acc[c4 * 4 + 0]);
            acc[c4 * 4 + 1] = fmaf(pk, t.y, acc[c4 * 4 + 1]);
            acc[c4 * 4 + 2] = fmaf(pk, t.z, acc[c4 * 4 + 2]);
            acc[c4 * 4 + 3] = fmaf(pk, t.w, acc[c4 * 4 + 3]);
        }
    }

    __shared__ float sm[8][DIM];
    float mine = 0.f;
    #pragma unroll
    for (int c = 0; c < DIM; c++) {
        float s = warp_sum(acc[c]);
        if (lane == c) mine = s;
    }
    sm[w][lane] = mine;
    __syncthreads();
    if (tid < DIM) {
        float t = 0.f;
        #pragma unroll
        for (int ww = 0; ww < 8; ww++) t += sm[ww][tid];
        g_M[r * DIM + tid] = t;
    }
}

// ---------------------------------------------------------------------
// K3: attention + fused Wo/LN1/FFN/LN2. 512 threads, 16 rows/block.
// phi term comes precomputed from g_P (tensor cores) — no phi inner loop.
// Dynamic smem (byte offsets):
//   0      sKT2 [2][32][32]u32   8192
//   8192   sVT2 [2][32][36]u32   9216  -> 17408
//   17408  sP   [2][16][64]f32   8192  -> 25600
//   25600  sS   [16][64]f32      4096  -> 29696
//   29696  sPQ  [16][64]f32      4096  -> 33792
//   33792  sM   [64][32]f32      8192  -> 41984
//   41984  sWo  4096             -> 46080
//   46080  sW1  16384            -> 62464
//   62464  sW2  16384            -> 78848
//   78848  sH   8192             -> 87040
//   87040  sA   2048             -> 89088
//   89088  sZ1  2048             -> 91136
//   91136  sb1  512              -> 91648
//   91648  sVec 768              -> 92416
// ---------------------------------------------------------------------
#define K3_SMEM_BYTES 92416

__device__ __forceinline__ void k3_stage_tile(int t, int b, int tid, int i0, unsigned smem_base)
{
    if (tid < 256) {
        int row = tid >> 3, c = tid & 7;
        unsigned d0 = smem_base + (unsigned)(b * 4096 + row * 128 + c * 16);
        CP_ASYNC16(d0, g_KT2 + row * (N_TOK / 2) + t * 32 + c * 4);
        int pr = tid >> 4, pc = tid & 15;
        unsigned d2 = smem_base + (unsigned)(17408 + b * 4096 + pr * 256 + pc * 16);
        CP_ASYNC16(d2, g_P + (size_t)(i0 + pr) * N_TOK + t * TJ + pc * 4);
    } else {
        int idx = tid - 256;
        int row = idx >> 3, c = idx & 7;
        unsigned d1 = smem_base + (unsigned)(8192 + b * 4608 + row * 144 + c * 16);
        CP_ASYNC16(d1, g_VT2 + row * (N_TOK / 2) + t * 32 + c * 4);
    }
}

__global__ void __launch_bounds__(512, 1) k3_attn(
    const int* __restrict__ mask,
    const float* __restrict__ Wo, const float* __restrict__ bo,
    const float* __restrict__ Z,
    const float* __restrict__ W1, const float* __restrict__ b1,
    const float* __restrict__ W2, const float* __restrict__ b2,
    const float* __restrict__ g1, const float* __restrict__ be1,
    const float* __restrict__ g2, const float* __restrict__ be2,
    float* __restrict__ out)
{
    extern __shared__ char sm_raw[];
    unsigned smem_base = (unsigned)__cvta_generic_to_shared(sm_raw);
    float*    sS    = (float*)(sm_raw + 25600);
    float*    sPQ   = (float*)(sm_raw + 29696);
    float*    sM    = (float*)(sm_raw + 33792);
    float*    sWo   = (float*)(sm_raw + 41984);
    float*    sW1   = (float*)(sm_raw + 46080);
    float*    sW2   = (float*)(sm_raw + 62464);
    float*    sH    = (float*)(sm_raw + 78848);
    float*    sA    = (float*)(sm_raw + 87040);
    float*    sZ1   = (float*)(sm_raw + 89088);
    float*    sb1   = (float*)(sm_raw + 91136);
    float*    sVec  = (float*)(sm_raw + 91648);

    int tid = threadIdx.x, lane = tid & 31, w = tid >> 5;
    int i0 = blockIdx.x * 16;

    // stage constants
    for (int idx = tid; idx < RFEAT * DIM; idx += 512) sM[idx] = g_M[idx];
    for (int idx = tid; idx < DIM * DIM; idx += 512) sWo[idx] = Wo[idx];
    for (int idx = tid; idx < DIM * HDIM; idx += 512) { sW1[idx] = W1[idx]; sW2[idx] = W2[idx]; }
    if (tid < HDIM) sb1[tid] = b1[tid];
    if (tid < DIM) {
        sVec[tid] = bo[tid];        sVec[32 + tid] = b2[tid];
        sVec[64 + tid] = g1[tid];   sVec[96 + tid] = be1[tid];
        sVec[128 + tid] = g2[tid];  sVec[160 + tid] = be2[tid];
    }

    int i = i0 + w;

    float q[DIM];
    #pragma unroll
    for (int k4 = 0; k4 < DIM / 4; k4++) {
        float4 t = *(const float4*)(g_Q + i * DIM + k4 * 4);
        q[k4 * 4 + 0] = t.x; q[k4 * 4 + 1] = t.y; q[k4 * 4 + 2] = t.z; q[k4 * 4 + 3] = t.w;
    }
    *(float2*)&sPQ[w * RFEAT + 2 * lane] = *(const float2*)(g_phiQ + i * RFEAT + 2 * lane);
    float zres = Z[i * DIM + lane];

    const int2* mrow2 = (const int2*)(mask + (size_t)i * N_TOK);
    int2 mv = mrow2[lane];
    float acc = 0.f;

    k3_stage_tile(0, 0, tid, i0, smem_base);
    CP_COMMIT();

    for (int t = 0; t < NTILES; t++) {
        CP_WAIT0();
        __syncthreads();
        if (t + 1 < NTILES) { k3_stage_tile(t + 1, (t + 1) & 1, tid, i0, smem_base); CP_COMMIT(); }

        int b = t & 1;
        const unsigned* KT = (const unsigned*)(sm_raw + b * 4096);
        const unsigned* VT = (const unsigned*)(sm_raw + 8192 + b * 4608) + lane * 36;
        float2 Pw = *(const float2*)(sm_raw + 17408 + b * 4096 + w * 256 + lane * 8);

        int2 nmv = make_int2(0, 0);
        if (t + 1 < NTILES) nmv = mrow2[(t + 1) * 32 + lane];

        // ---- exp part: j-pair per thread, bf16 K tiles ----
        float eA0 = 0.f, eA1 = 0.f, eB0 = 0.f, eB1 = 0.f;
        #pragma unroll
        for (int k = 0; k < DIM; k += 2) {
            unsigned u0 = KT[k * 32 + lane];
            unsigned u1 = KT[(k + 1) * 32 + lane];
            eA0 += fast_ex2(q[k]     * BFLO(u0));
            eB0 += fast_ex2(q[k]     * BFHI(u0));
            eA1 += fast_ex2(q[k + 1] * BFLO(u1));
            eB1 += fast_ex2(q[k + 1] * BFHI(u1));
        }

        float2 sv;
        sv.x = (mv.x == 0) ? ((eA0 + eA1) - Pw.x) : 0.f;
        sv.y = (mv.y == 0) ? ((eB0 + eB1) - Pw.y) : 0.f;
        *(float2*)&sS[w * TJ + 2 * lane] = sv;
        __syncwarp();

        // ---- AV: lane = output column c, V^T bf16x2 tiles ----
        const float4* SS = (const float4*)&sS[w * TJ];
        #pragma unroll
        for (int j8 = 0; j8 < 8; j8++) {
            uint4 v = *(const uint4*)(VT + j8 * 4);
            float4 s0 = SS[2 * j8], s1 = SS[2 * j8 + 1];
            acc = fmaf(s0.x, BFLO(v.x), acc); acc = fmaf(s0.y, BFHI(v.x), acc);
            acc = fmaf(s0.z, BFLO(v.y), acc); acc = fmaf(s0.w, BFHI(v.y), acc);
            acc = fmaf(s1.x, BFLO(v.z), acc); acc = fmaf(s1.y, BFHI(v.z), acc);
            acc = fmaf(s1.z, BFLO(v.w), acc); acc = fmaf(s1.w, BFHI(v.w), acc);
        }
        mv = nmv;
        __syncwarp();
    }

    // ---- epilogue: + low-rank, normalize, @Wo+bo, LN1, FFN, LN2 ----
    float lr = 0.f;
    #pragma unroll
    for (int r = 0; r < RFEAT; r++) lr = fmaf(sPQ[w * RFEAT + r], sM[r * DIM + lane], lr);

    float attn = acc + lr;
    float denom = fmaxf(warp_sum(attn), 1e-6f);
    float a = attn / denom;

    sA[w * DIM + lane] = a;
    __syncwarp();
    float o = sVec[lane];   // bo
    #pragma unroll
    for (int c = 0; c < DIM; c++) o = fmaf(sA[w * DIM + c], sWo[c * DIM + lane], o);

    // LN1
    float x = zres + o;
    float mu = warp_sum(x) * (1.f / 32.f);
    float dd = x - mu;
    float var = warp_sum(dd * dd) * (1.f / 32.f);
    float z1 = dd * rsqrtf(var + 1e-5f) * sVec[64 + lane] + sVec[96 + lane];
    sZ1[w * DIM + lane] = z1;
    __syncwarp();

    // FFN up + relu
    float h[4];
    #pragma unroll
    for (int u = 0; u < 4; u++) h[u] = sb1[lane + u * 32];
    #pragma unroll
    for (int k = 0; k < DIM; k++) {
        float zk = sZ1[w * DIM + k];
        #pragma unroll
        for (int u = 0; u < 4; u++) h[u] = fmaf(zk, sW1[k * HDIM + lane + u * 32], h[u]);
    }
    #pragma unroll
    for (int u = 0; u < 4; u++) sH[w * HDIM + lane + u * 32] = fmaxf(h[u], 0.f);
    __syncwarp();

    // FFN down
    float o0 = sVec[32 + lane], o1 = 0.f, o2 = 0.f, o3 = 0.f;
    #pragma unroll
    for (int j = 0; j < HDIM; j += 4) {
        o0 = fmaf(sH[w * HDIM + j + 0], sW2[(j + 0) * DIM + lane], o0);
        o1 = fmaf(sH[w * HDIM + j + 1], sW2[(j + 1) * DIM + lane], o1);
        o2 = fmaf(sH[w * HDIM + j + 2], sW2[(j + 2) * DIM + lane], o2);
        o3 = fmaf(sH[w * HDIM + j + 3], sW2[(j + 3) * DIM + lane], o3);
    }
    float y = z1 + ((o0 + o1) + (o2 + o3));

    // LN2
    float mu2 = warp_sum(y) * (1.f / 32.f);
    float dd2 = y - mu2;
    float var2 = warp_sum(dd2 * dd2) * (1.f / 32.f);
    out[i * DIM + lane] = dd2 * rsqrtf(var2 + 1e-5f) * sVec[128 + lane] + sVec[160 + lane];
}

// ---------------------------------------------------------------------
extern "C" void kernel_launch(void* const* d_in, const int* in_sizes, int n_in,
                              void* d_out, int out_size)
{
    const float* Z    = (const float*)d_in[0];
    const int*   mask = (const int*)  d_in[1];
    const float* Wq = (const float*)d_in[2],  *bq = (const float*)d_in[3];
    const float* Wk = (const float*)d_in[4],  *bk = (const float*)d_in[5];
    const float* Wv = (const float*)d_in[6],  *bv = (const float*)d_in[7];
    const float* Wo = (const float*)d_in[8],  *bo = (const float*)d_in[9];
    const float* W1 = (const float*)d_in[10], *b1 = (const float*)d_in[11];
    const float* W2 = (const float*)d_in[12], *b2 = (const float*)d_in[13];
    const float* g1 = (const float*)d_in[14], *be1 = (const float*)d_in[15];
    const float* g2 = (const float*)d_in[16], *be2 = (const float*)d_in[17];
    const float* omega = (const float*)d_in[18];

    cudaFuncSetAttribute(k3_attn, cudaFuncAttributeMaxDynamicSharedMemorySize, K3_SMEM_BYTES);

    k1_proj<<<N_TOK / 16, 512>>>(Z, Wq, bq, Wk, bk, Wv, bv, omega);
    kP_phigemm<<<dim3(N_TOK / 128, N_TOK / 64), 256>>>();
    k2_kv<<<RFEAT, 256>>>();
    k3_attn<<<N_TOK / 16, 512, K3_SMEM_BYTES>>>(mask, Wo, bo, Z,
                                                W1, b1, W2, b2,
                                                g1, be1, g2, be2, (float*)d_out);
}

// round 9
// speedup vs baseline: 1.1324x; 1.0263x over previous
#include <cuda_runtime.h>
#include <cuda_bf16.h>
#include <cstdint>

#define N_TOK 2048
#define DIM   32
#define RFEAT 64
#define HDIM  128
#define NSUP  (N_TOK / 128)     // 16 supertiles of 128 j

// ---------- scratch (device globals; no allocation allowed) ----------
__device__ __align__(16) float    g_Q[N_TOK * DIM];
__device__ __align__(16) float    g_V[N_TOK * DIM];
__device__ __align__(16) float    g_phiQ[N_TOK * RFEAT];
__device__ __align__(16) float    g_phiK[N_TOK * RFEAT];         // fp32, for k2
__device__ __align__(16) unsigned g_phiQh2[N_TOK * (RFEAT / 2)]; // row-major bf16x2 r-pairs
__device__ __align__(16) unsigned g_phiKh2[N_TOK * (RFEAT / 2)];
__device__ __align__(16) unsigned g_KT2[DIM * (N_TOK / 2)];      // [k][j2] bf16x2 j-pairs (scaled K)
__device__ __align__(16) unsigned g_VT2[DIM * (N_TOK / 2)];      // [c][j2] bf16x2 j-pairs
__device__ __align__(16) float    g_M[RFEAT * DIM];              // phi_K^T @ V
__device__ __align__(16) float    g_P[N_TOK * N_TOK];            // phiQ @ phiK^T (16MB)

__device__ __forceinline__ float fast_ex2(float x) {
    float y;
    asm("ex2.approx.ftz.f32 %0, %1;" : "=f"(y) : "f"(x));
    return y;
}
__device__ __forceinline__ float warp_sum(float v) {
    v += __shfl_xor_sync(0xffffffffu, v, 16);
    v += __shfl_xor_sync(0xffffffffu, v, 8);
    v += __shfl_xor_sync(0xffffffffu, v, 4);
    v += __shfl_xor_sync(0xffffffffu, v, 2);
    v += __shfl_xor_sync(0xffffffffu, v, 1);
    return v;
}
__device__ __forceinline__ unsigned packbf(float a, float b) {
    __nv_bfloat162 h = __floats2bfloat162_rn(a, b);
    return *reinterpret_cast<unsigned*>(&h);
}
#define BFLO(u) __uint_as_float((u) << 16)
#define BFHI(u) __uint_as_float((u) & 0xffff0000u)

#define CP_ASYNC16(dst_s, src_g) \
    asm volatile("cp.async.cg.shared.global [%0], [%1], 16;" :: "r"(dst_s), "l"(src_g))
#define CP_COMMIT() asm volatile("cp.async.commit_group;")
#define CP_WAIT0()  asm volatile("cp.async.wait_group 0;" ::: "memory")

#define L2E    1.4426950408889634f
#define KSCALE ((float)(1.4426950408889634 / 5.6568542494923806)) // log2e/sqrt(32)

// ---------------------------------------------------------------------
// K1: warp-per-row QKV + norms + random features (proven version).
// ---------------------------------------------------------------------
__global__ void __launch_bounds__(512) k1_proj(const float* __restrict__ Z,
                        const float* __restrict__ Wq, const float* __restrict__ bq,
                        const float* __restrict__ Wk, const float* __restrict__ bk,
                        const float* __restrict__ Wv, const float* __restrict__ bv,
                        const float* __restrict__ omega)
{
    __shared__ float sW[3][DIM * DIM];
    __shared__ float sB[3][DIM];
    __shared__ float sOm[DIM * RFEAT];
    __shared__ float sRow[16][DIM];
    __shared__ float sAn[16][DIM];
    __shared__ float sK[16][33];
    __shared__ float sVv[16][33];

    int tid = threadIdx.x, lane = tid & 31, w = tid >> 5;
    for (int idx = tid; idx < DIM * DIM; idx += 512) {
        sW[0][idx] = Wq[idx]; sW[1][idx] = Wk[idx]; sW[2][idx] = Wv[idx];
    }
    for (int idx = tid; idx < DIM * RFEAT; idx += 512) sOm[idx] = omega[idx];
    if (tid < DIM) { sB[0][tid] = bq[tid]; sB[1][tid] = bk[tid]; sB[2][tid] = bv[tid]; }

    int i0 = blockIdx.x * 16;
    int i = i0 + w;
    float zk = Z[i * DIM + lane];
    __syncthreads();

    sRow[w][lane] = zk;
    __syncwarp();

    float a[3];
    #pragma unroll
    for (int p = 0; p < 3; p++) {
        float s0 = sB[p][lane], s1 = 0.f;
        #pragma unroll
        for (int k = 0; k < DIM; k += 2) {
            s0 = fmaf(sRow[w][k],     sW[p][k * DIM + lane],       s0);
            s1 = fmaf(sRow[w][k + 1], sW[p][(k + 1) * DIM + lane], s1);
        }
        a[p] = s0 + s1;
    }
    g_Q[i * DIM + lane] = a[0];
    g_V[i * DIM + lane] = a[2];
    sK[w][lane]  = a[1] * KSCALE;
    sVv[w][lane] = a[2];

    #pragma unroll
    for (int p = 0; p < 2; p++) {
        float v = a[p];
        float ss = warp_sum(v * v);
        float an = v * (1.f / fmaxf(sqrtf(ss), 1e-6f));
        sAn[w][lane] = an;
        __syncwarp();
        float d0 = 0.f, d1 = 0.f, d2 = 0.f, d3 = 0.f;
        #pragma unroll
        for (int k = 0; k < DIM; k += 2) {
            float ab0 = sAn[w][k], ab1 = sAn[w][k + 1];
            float2 om0 = *(const float2*)&sOm[k * RFEAT + 2 * lane];
            float2 om1 = *(const float2*)&sOm[(k + 1) * RFEAT + 2 * lane];
            d0 = fmaf(ab0, om0.x, d0); d1 = fmaf(ab0, om0.y, d1);
            d2 = fmaf(ab1, om1.x, d2); d3 = fmaf(ab1, om1.y, d3);
        }
        float e0 = fast_ex2((d0 + d2) * L2E) * 0.125f;  // exp(d)/sqrt(r), r=64
        float e1 = fast_ex2((d1 + d3) * L2E) * 0.125f;
        float2 ph; ph.x = e0; ph.y = e1;
        if (p == 0) {
            *(float2*)&g_phiQ[i * RFEAT + 2 * lane] = ph;
            g_phiQh2[i * (RFEAT / 2) + lane] = packbf(e0, e1);
        } else {
            *(float2*)&g_phiK[i * RFEAT + 2 * lane] = ph;
            g_phiKh2[i * (RFEAT / 2) + lane] = packbf(e0, e1);
        }
        __syncwarp();
    }

    __syncthreads();
    if (tid < 256) {
        int k = tid >> 3, p = tid & 7;
        int dst = k * (N_TOK / 2) + (i0 >> 1) + p;
        g_KT2[dst] = packbf(sK[2 * p][k],  sK[2 * p + 1][k]);
        g_VT2[dst] = packbf(sVv[2 * p][k], sVv[2 * p + 1][k]);
    }
}

// ---------------------------------------------------------------------
// kP: P = phiQ @ phiK^T via warp-level mma.sync bf16 (fp32 accum).
// ---------------------------------------------------------------------
__global__ void __launch_bounds__(256) kP_phigemm()
{
    int tid = threadIdx.x, lane = tid & 31, wi = tid >> 5;
    int g   = lane >> 2;
    int tig = lane & 3;
    int ib  = blockIdx.x * 128 + wi * 16;
    int j0  = blockIdx.y * 64;

    float d[8][4];
    #pragma unroll
    for (int nc = 0; nc < 8; nc++)
        #pragma unroll
        for (int u = 0; u < 4; u++) d[nc][u] = 0.f;

    #pragma unroll
    for (int ks = 0; ks < 4; ks++) {
        int kp = ks * 8 + tig;
        unsigned a0 = g_phiQh2[(ib + g)     * 32 + kp];
        unsigned a1 = g_phiQh2[(ib + g + 8) * 32 + kp];
        unsigned a2 = g_phiQh2[(ib + g)     * 32 + kp + 4];
        unsigned a3 = g_phiQh2[(ib + g + 8) * 32 + kp + 4];
        #pragma unroll
        for (int nc = 0; nc < 8; nc++) {
            int jn = j0 + nc * 8 + g;
            unsigned b0 = g_phiKh2[jn * 32 + kp];
            unsigned b1 = g_phiKh2[jn * 32 + kp + 4];
            asm volatile(
                "mma.sync.aligned.m16n8k16.row.col.f32.bf16.bf16.f32 "
                "{%0,%1,%2,%3}, {%4,%5,%6,%7}, {%8,%9}, {%0,%1,%2,%3};"
                : "+f"(d[nc][0]), "+f"(d[nc][1]), "+f"(d[nc][2]), "+f"(d[nc][3])
                : "r"(a0), "r"(a1), "r"(a2), "r"(a3), "r"(b0), "r"(b1));
        }
    }

    #pragma unroll
    for (int nc = 0; nc < 8; nc++) {
        int jc = j0 + nc * 8 + tig * 2;
        *(float2*)(g_P + (size_t)(ib + g)     * N_TOK + jc) = make_float2(d[nc][0], d[nc][1]);
        *(float2*)(g_P + (size_t)(ib + g + 8) * N_TOK + jc) = make_float2(d[nc][2], d[nc][3]);
    }
}

// ---------------------------------------------------------------------
// K2: M = phi_K^T @ V   [64 x 32]. One block per r.
// ---------------------------------------------------------------------
__global__ void k2_kv()
{
    int r = blockIdx.x;
    int tid = threadIdx.x, lane = tid & 31, w = tid >> 5;

    float acc[DIM];
    #pragma unroll
    for (int c = 0; c < DIM; c++) acc[c] = 0.f;

    for (int n = tid; n < N_TOK; n += 256) {
        float pk = g_phiK[n * RFEAT + r];
        const float4* v4 = reinterpret_cast<const float4*>(g_V + n * DIM);
        #pragma unroll
        for (int c4 = 0; c4 < DIM / 4; c4++) {
            float4 t = v4[c4];
            acc[c4 * 4 + 0] = fmaf(pk, t.x, acc[c4 * 4 + 0]);
            acc[c4 * 4 + 1] = fmaf(pk, t.y, acc[c4 * 4 + 1]);
            acc[c4 * 4 + 2] = fmaf(pk, t.z, acc[c4 * 4 + 2]);
            acc[c4 * 4 + 3] = fmaf(pk, t.w, acc[c4 * 4 + 3]);
        }
    }

    __shared__ float sm[8][DIM];
    float mine = 0.f;
    #pragma unroll
    for (int c = 0; c < DIM; c++) {
        float s = warp_sum(acc[c]);
        if (lane == c) mine = s;
    }
    sm[w][lane] = mine;
    __syncthreads();
    if (tid < DIM) {
        float t = 0.f;
        #pragma unroll
        for (int ww = 0; ww < 8; ww++) t += sm[ww][tid];
        g_M[r * DIM + tid] = t;
    }
}

// ---------------------------------------------------------------------
// K3: attention + fused epilogue. 1024 threads = 32 warps, 16 rows/block,
// warp pair per row (w>>1 = row, w&1 = j-half of a 128-j supertile).
// Dynamic smem (byte offsets):
//   0      sKT2 [2][32][64]u32  16384
//   16384  sVT2 [2][32][68]u32  17408 -> 33792   (stride 68 u32, pad)
//   33792  sP   [2][16][128]f32 16384 -> 50176
//   50176  sS   [16][128]f32     8192 -> 58368
//   58368  sQ   [16][32]f32      2048 -> 60416
//   60416  sPQ  [16][64]f32      4096 -> 64512
//   64512  sWo  [32][32]f32      4096 -> 68608
//   68608  sAcc [32][32]f32      4096 -> 72704
//   72704  sVec [6][32]f32        768 -> 73472
//   73472  sb1  [128]f32          512 -> 73984
//   73984  sZ1  [16][32]f32      2048 -> 76032
// Epilogue overlay in [0, 50176): sM@0 (8192), sW1@8192 (16384),
//   sW2@24576 (16384), sH@40960 (8192) -> 49152.
// ---------------------------------------------------------------------
#define K3_SMEM_BYTES 76032

__device__ __forceinline__ void k3_stage(int t, int b, int tid, int i0, unsigned base)
{
    if (tid < 512) {
        int row = tid >> 4, c = tid & 15;
        CP_ASYNC16(base + (unsigned)(b * 8192 + row * 256 + c * 16),
                   g_KT2 + row * (N_TOK / 2) + t * 64 + c * 4);
        int pr = tid >> 5, pc = tid & 31;
        CP_ASYNC16(base + (unsigned)(33792 + b * 8192 + pr * 512 + pc * 16),
                   g_P + (size_t)(i0 + pr) * N_TOK + t * 128 + pc * 4);
    } else {
        int idx = tid - 512;
        int row = idx >> 4, c = idx & 15;
        CP_ASYNC16(base + (unsigned)(16384 + b * 8704 + row * 272 + c * 16),
                   g_VT2 + row * (N_TOK / 2) + t * 64 + c * 4);
    }
}

__global__ void __launch_bounds__(1024, 1) k3_attn(
    const int* __restrict__ mask,
    const float* __restrict__ Wo, const float* __restrict__ bo,
    const float* __restrict__ Z,
    const float* __restrict__ W1, const float* __restrict__ b1,
    const float* __restrict__ W2, const float* __restrict__ b2,
    const float* __restrict__ g1, const float* __restrict__ be1,
    const float* __restrict__ g2, const float* __restrict__ be2,
    float* __restrict__ out)
{
    extern __shared__ char sm_raw[];
    unsigned smem_base = (unsigned)__cvta_generic_to_shared(sm_raw);
    float* sS   = (float*)(sm_raw + 50176);
    float* sQ   = (float*)(sm_raw + 58368);
    float* sPQ  = (float*)(sm_raw + 60416);
    float* sWo  = (float*)(sm_raw + 64512);
    float* sAcc = (float*)(sm_raw + 68608);
    float* sVec = (float*)(sm_raw + 72704);
    float* sb1  = (float*)(sm_raw + 73472);
    float* sZ1  = (float*)(sm_raw + 73984);
    // epilogue overlay
    float* sM   = (float*)(sm_raw);
    float* sW1  = (float*)(sm_raw + 8192);
    float* sW2  = (float*)(sm_raw + 24576);
    float* sH   = (float*)(sm_raw + 40960);

    int tid = threadIdx.x, lane = tid & 31, w = tid >> 5;
    int r16 = w >> 1, h = w & 1;
    int i0 = blockIdx.x * 16;
    int i  = i0 + r16;

    // stage persistent data
    if (tid < 512) sQ[tid] = g_Q[i0 * DIM + tid];
    sPQ[tid] = g_phiQ[i0 * RFEAT + tid];
    for (int idx = tid; idx < DIM * DIM; idx += 1024) sWo[idx] = Wo[idx];
    if (tid < HDIM) sb1[tid] = b1[tid];
    if (tid < DIM) {
        sVec[tid] = bo[tid];        sVec[32 + tid] = b2[tid];
        sVec[64 + tid] = g1[tid];   sVec[96 + tid] = be1[tid];
        sVec[128 + tid] = g2[tid];  sVec[160 + tid] = be2[tid];
    }

    const int2* mrow2 = (const int2*)(mask + (size_t)i * N_TOK);
    float acc = 0.f;

    k3_stage(0, 0, tid, i0, smem_base);
    CP_COMMIT();

    for (int t = 0; t < NSUP; t++) {
        CP_WAIT0();
        __syncthreads();
        if (t + 1 < NSUP) { k3_stage(t + 1, (t + 1) & 1, tid, i0, smem_base); CP_COMMIT(); }

        int b = t & 1;
        const unsigned* KT = (const unsigned*)(sm_raw + b * 8192) + h * 32 + lane;
        const unsigned* VT = (const unsigned*)(sm_raw + 16384 + b * 8704) + lane * 68 + h * 32;
        float2 Pw = *(const float2*)(sm_raw + 33792 + b * 8192 + r16 * 512 + (h * 64 + 2 * lane) * 4);
        int2 mv = mrow2[t * 64 + h * 32 + lane];

        // ---- exp part: j-pair per thread, bf16 K tiles, q from smem ----
        float eA0 = 0.f, eA1 = 0.f, eB0 = 0.f, eB1 = 0.f;
        #pragma unroll
        for (int k = 0; k < DIM; k += 2) {
            float2 qq = *(const float2*)&sQ[r16 * DIM + k];
            unsigned u0 = KT[k * 64];
            unsigned u1 = KT[(k + 1) * 64];
            eA0 += fast_ex2(qq.x * BFLO(u0));
            eB0 += fast_ex2(qq.x * BFHI(u0));
            eA1 += fast_ex2(qq.y * BFLO(u1));
            eB1 += fast_ex2(qq.y * BFHI(u1));
        }

        float2 sv;
        sv.x = (mv.x == 0) ? ((eA0 + eA1) - Pw.x) : 0.f;
        sv.y = (mv.y == 0) ? ((eB0 + eB1) - Pw.y) : 0.f;
        *(float2*)&sS[r16 * 128 + h * 64 + 2 * lane] = sv;
        __syncwarp();

        // ---- AV over own 64-j half: lane = output column c ----
        const float4* SS = (const float4*)&sS[r16 * 128 + h * 64];
        #pragma unroll
        for (int j8 = 0; j8 < 8; j8++) {
            uint4 v = *(const uint4*)(VT + j8 * 4);
            float4 s0 = SS[2 * j8], s1 = SS[2 * j8 + 1];
            acc = fmaf(s0.x, BFLO(v.x), acc); acc = fmaf(s0.y, BFHI(v.x), acc);
            acc = fmaf(s0.z, BFLO(v.y), acc); acc = fmaf(s0.w, BFHI(v.y), acc);
            acc = fmaf(s1.x, BFLO(v.z), acc); acc = fmaf(s1.y, BFHI(v.z), acc);
            acc = fmaf(s1.z, BFLO(v.w), acc); acc = fmaf(s1.w, BFHI(v.w), acc);
        }
        __syncwarp();
    }

    // ---- epilogue ----
    __syncthreads();           // last tile compute done; tile buffers now free
    // overlay staging (all 1024 threads)
    for (int idx = tid; idx < RFEAT * DIM; idx += 1024) sM[idx] = g_M[idx];
    for (int idx = tid; idx < DIM * HDIM; idx += 1024) { sW1[idx] = W1[idx]; sW2[idx] = W2[idx]; }
    sAcc[w * 32 + lane] = acc;
    __syncthreads();

    if (h == 0) {
        float lr = 0.f;
        #pragma unroll
        for (int r = 0; r < RFEAT; r++) lr = fmaf(sPQ[r16 * RFEAT + r], sM[r * DIM + lane], lr);

        float attn = sAcc[w * 32 + lane] + sAcc[(w + 1) * 32 + lane] + lr;
        float denom = fmaxf(warp_sum(attn), 1e-6f);
        float a = attn / denom;

        sAcc[w * 32 + lane] = a;     // reuse as per-row staging
        __syncwarp();
        float o = sVec[lane];        // bo
        #pragma unroll
        for (int c = 0; c < DIM; c++) o = fmaf(sAcc[w * 32 + c], sWo[c * DIM + lane], o);

        // LN1
        float x = Z[i * DIM + lane] + o;
        float mu = warp_sum(x) * (1.f / 32.f);
        float dd = x - mu;
        float var = warp_sum(dd * dd) * (1.f / 32.f);
        float z1 = dd * rsqrtf(var + 1e-5f) * sVec[64 + lane] + sVec[96 + lane];
        sZ1[r16 * DIM + lane] = z1;
        __syncwarp();

        // FFN up + relu
        float hh[4];
        #pragma unroll
        for (int u = 0; u < 4; u++) hh[u] = sb1[lane + u * 32];
        #pragma unroll
        for (int k = 0; k < DIM; k++) {
            float zk = sZ1[r16 * DIM + k];
            #pragma unroll
            for (int u = 0; u < 4; u++) hh[u] = fmaf(zk, sW1[k * HDIM + lane + u * 32], hh[u]);
        }
        #pragma unroll
        for (int u = 0; u < 4; u++) sH[r16 * HDIM + lane + u * 32] = fmaxf(hh[u], 0.f);
        __syncwarp();

        // FFN down
        float o0 = sVec[32 + lane], o1 = 0.f, o2 = 0.f, o3 = 0.f;
        #pragma unroll
        for (int j = 0; j < HDIM; j += 4) {
            o0 = fmaf(sH[r16 * HDIM + j + 0], sW2[(j + 0) * DIM + lane], o0);
            o1 = fmaf(sH[r16 * HDIM + j + 1], sW2[(j + 1) * DIM + lane], o1);
            o2 = fmaf(sH[r16 * HDIM + j + 2], sW2[(j + 2) * DIM + lane], o2);
            o3 = fmaf(sH[r16 * HDIM + j + 3], sW2[(j + 3) * DIM + lane], o3);
        }
        float y = z1 + ((o0 + o1) + (o2 + o3));

        // LN2
        float mu2 = warp_sum(y) * (1.f / 32.f);
        float dd2 = y - mu2;
        float var2 = warp_sum(dd2 * dd2) * (1.f / 32.f);
        out[i * DIM + lane] = dd2 * rsqrtf(var2 + 1e-5f) * sVec[128 + lane] + sVec[160 + lane];
    }
}

// ---------------------------------------------------------------------
extern "C" void kernel_launch(void* const* d_in, const int* in_sizes, int n_in,
                              void* d_out, int out_size)
{
    const float* Z    = (const float*)d_in[0];
    const int*   mask = (const int*)  d_in[1];
    const float* Wq = (const float*)d_in[2],  *bq = (const float*)d_in[3];
    const float* Wk = (const float*)d_in[4],  *bk = (const float*)d_in[5];
    const float* Wv = (const float*)d_in[6],  *bv = (const float*)d_in[7];
    const float* Wo = (const float*)d_in[8],  *bo = (const float*)d_in[9];
    const float* W1 = (const float*)d_in[10], *b1 = (const float*)d_in[11];
    const float* W2 = (const float*)d_in[12], *b2 = (const float*)d_in[13];
    const float* g1 = (const float*)d_in[14], *be1 = (const float*)d_in[15];
    const float* g2 = (const float*)d_in[16], *be2 = (const float*)d_in[17];
    const float* omega = (const float*)d_in[18];

    cudaFuncSetAttribute(k3_attn, cudaFuncAttributeMaxDynamicSharedMemorySize, K3_SMEM_BYTES);

    k1_proj<<<N_TOK / 16, 512>>>(Z, Wq, bq, Wk, bk, Wv, bv, omega);
    kP_phigemm<<<dim3(N_TOK / 128, N_TOK / 64), 256>>>();
    k2_kv<<<RFEAT, 256>>>();
    k3_attn<<<N_TOK / 16, 1024, K3_SMEM_BYTES>>>(mask, Wo, bo, Z,
                                                 W1, b1, W2, b2,
                                                 g1, be1, g2, be2, (float*)d_out);
}

// round 10
// speedup vs baseline: 1.1598x; 1.0242x over previous
#include <cuda_runtime.h>
#include <cuda_bf16.h>
#include <cuda_fp16.h>
#include <cstdint>

#define N_TOK 2048
#define DIM   32
#define RFEAT 64
#define HDIM  128
#define NSUP  (N_TOK / 128)     // 16 supertiles of 128 j

// ---------- scratch (device globals; no allocation allowed) ----------
__device__ __align__(16) float    g_Q[N_TOK * DIM];
__device__ __align__(16) float    g_V[N_TOK * DIM];
__device__ __align__(16) float    g_phiQ[N_TOK * RFEAT];
__device__ __align__(16) float    g_phiK[N_TOK * RFEAT];         // fp32, for k2
__device__ __align__(16) unsigned g_phiQh2[N_TOK * (RFEAT / 2)]; // row-major bf16x2 r-pairs
__device__ __align__(16) unsigned g_phiKh2[N_TOK * (RFEAT / 2)];
__device__ __align__(16) unsigned g_KTh2[(DIM / 2) * N_TOK];     // [k2][j] fp16x2 k-pairs (scaled K)
__device__ __align__(16) unsigned g_Qh2[N_TOK * (DIM / 2)];      // [i][k2] fp16x2 k-pairs
__device__ __align__(16) unsigned g_VT2[DIM * (N_TOK / 2)];      // [c][j2] bf16x2 j-pairs
__device__ __align__(16) float    g_M[RFEAT * DIM];              // phi_K^T @ V
__device__ __align__(16) float    g_P[N_TOK * N_TOK];            // phiQ @ phiK^T (16MB)

__device__ __forceinline__ float fast_ex2(float x) {
    float y;
    asm("ex2.approx.ftz.f32 %0, %1;" : "=f"(y) : "f"(x));
    return y;
}
// dual fp16 ex2: one MUFU op, two exponentials
__device__ __forceinline__ __half2 h2ex2(__half2 x) {
    __half2 y;
    asm("ex2.approx.f16x2 %0, %1;" : "=r"(*(unsigned*)&y) : "r"(*(unsigned*)&x));
    return y;
}
__device__ __forceinline__ __half2 u2h(unsigned u) { return *reinterpret_cast<__half2*>(&u); }

__device__ __forceinline__ float warp_sum(float v) {
    v += __shfl_xor_sync(0xffffffffu, v, 16);
    v += __shfl_xor_sync(0xffffffffu, v, 8);
    v += __shfl_xor_sync(0xffffffffu, v, 4);
    v += __shfl_xor_sync(0xffffffffu, v, 2);
    v += __shfl_xor_sync(0xffffffffu, v, 1);
    return v;
}
__device__ __forceinline__ unsigned packbf(float a, float b) {
    __nv_bfloat162 h = __floats2bfloat162_rn(a, b);
    return *reinterpret_cast<unsigned*>(&h);
}
__device__ __forceinline__ unsigned packh(float a, float b) {
    __half2 h = __floats2half2_rn(a, b);
    return *reinterpret_cast<unsigned*>(&h);
}
#define BFLO(u) __uint_as_float((u) << 16)
#define BFHI(u) __uint_as_float((u) & 0xffff0000u)

#define CP_ASYNC16(dst_s, src_g) \
    asm volatile("cp.async.cg.shared.global [%0], [%1], 16;" :: "r"(dst_s), "l"(src_g))
#define CP_COMMIT() asm volatile("cp.async.commit_group;")
#define CP_WAIT0()  asm volatile("cp.async.wait_group 0;" ::: "memory")

#define L2E    1.4426950408889634f
#define KSCALE ((float)(1.4426950408889634 / 5.6568542494923806)) // log2e/sqrt(32)

// ---------------------------------------------------------------------
// K1: warp-per-row QKV + norms + random features.
// Emits: fp16x2 K^T k-pairs [k2][j], fp16x2 q k-pairs [i][k2],
//        bf16x2 V^T j-pairs, bf16x2 phi rows.
// ---------------------------------------------------------------------
__global__ void __launch_bounds__(512) k1_proj(const float* __restrict__ Z,
                        const float* __restrict__ Wq, const float* __restrict__ bq,
                        const float* __restrict__ Wk, const float* __restrict__ bk,
                        const float* __restrict__ Wv, const float* __restrict__ bv,
                        const float* __restrict__ omega)
{
    __shared__ float sW[3][DIM * DIM];
    __shared__ float sB[3][DIM];
    __shared__ float sOm[DIM * RFEAT];
    __shared__ float sRow[16][DIM];
    __shared__ float sAn[16][DIM];
    __shared__ float sK[16][33];
    __shared__ float sVv[16][33];
    __shared__ float sQf[16][33];

    int tid = threadIdx.x, lane = tid & 31, w = tid >> 5;
    for (int idx = tid; idx < DIM * DIM; idx += 512) {
        sW[0][idx] = Wq[idx]; sW[1][idx] = Wk[idx]; sW[2][idx] = Wv[idx];
    }
    for (int idx = tid; idx < DIM * RFEAT; idx += 512) sOm[idx] = omega[idx];
    if (tid < DIM) { sB[0][tid] = bq[tid]; sB[1][tid] = bk[tid]; sB[2][tid] = bv[tid]; }

    int i0 = blockIdx.x * 16;
    int i = i0 + w;
    float zk = Z[i * DIM + lane];
    __syncthreads();

    sRow[w][lane] = zk;
    __syncwarp();

    float a[3];
    #pragma unroll
    for (int p = 0; p < 3; p++) {
        float s0 = sB[p][lane], s1 = 0.f;
        #pragma unroll
        for (int k = 0; k < DIM; k += 2) {
            s0 = fmaf(sRow[w][k],     sW[p][k * DIM + lane],       s0);
            s1 = fmaf(sRow[w][k + 1], sW[p][(k + 1) * DIM + lane], s1);
        }
        a[p] = s0 + s1;
    }
    g_Q[i * DIM + lane] = a[0];
    g_V[i * DIM + lane] = a[2];
    sQf[w][lane] = a[0];
    sK[w][lane]  = a[1] * KSCALE;
    sVv[w][lane] = a[2];

    #pragma unroll
    for (int p = 0; p < 2; p++) {
        float v = a[p];
        float ss = warp_sum(v * v);
        float an = v * (1.f / fmaxf(sqrtf(ss), 1e-6f));
        sAn[w][lane] = an;
        __syncwarp();
        float d0 = 0.f, d1 = 0.f, d2 = 0.f, d3 = 0.f;
        #pragma unroll
        for (int k = 0; k < DIM; k += 2) {
            float ab0 = sAn[w][k], ab1 = sAn[w][k + 1];
            float2 om0 = *(const float2*)&sOm[k * RFEAT + 2 * lane];
            float2 om1 = *(const float2*)&sOm[(k + 1) * RFEAT + 2 * lane];
            d0 = fmaf(ab0, om0.x, d0); d1 = fmaf(ab0, om0.y, d1);
            d2 = fmaf(ab1, om1.x, d2); d3 = fmaf(ab1, om1.y, d3);
        }
        float e0 = fast_ex2((d0 + d2) * L2E) * 0.125f;  // exp(d)/sqrt(r), r=64
        float e1 = fast_ex2((d1 + d3) * L2E) * 0.125f;
        float2 ph; ph.x = e0; ph.y = e1;
        if (p == 0) {
            *(float2*)&g_phiQ[i * RFEAT + 2 * lane] = ph;
            g_phiQh2[i * (RFEAT / 2) + lane] = packbf(e0, e1);
        } else {
            *(float2*)&g_phiK[i * RFEAT + 2 * lane] = ph;
            g_phiKh2[i * (RFEAT / 2) + lane] = packbf(e0, e1);
        }
        __syncwarp();
    }

    __syncthreads();
    if (tid < 256) {
        // V^T bf16x2 j-pairs
        int k = tid >> 3, p = tid & 7;
        g_VT2[k * (N_TOK / 2) + (i0 >> 1) + p] = packbf(sVv[2 * p][k], sVv[2 * p + 1][k]);
        // K^T fp16x2 k-pairs [k2][j] and q fp16x2 k-pairs [i][k2]
        int k2 = tid >> 4, r = tid & 15;
        g_KTh2[k2 * N_TOK + i0 + r] = packh(sK[r][2 * k2], sK[r][2 * k2 + 1]);
        g_Qh2[(i0 + r) * (DIM / 2) + k2] = packh(sQf[r][2 * k2], sQf[r][2 * k2 + 1]);
    }
}

// ---------------------------------------------------------------------
// kP: P = phiQ @ phiK^T via warp-level mma.sync bf16 (fp32 accum).
// ---------------------------------------------------------------------
__global__ void __launch_bounds__(256) kP_phigemm()
{
    int tid = threadIdx.x, lane = tid & 31, wi = tid >> 5;
    int g   = lane >> 2;
    int tig = lane & 3;
    int ib  = blockIdx.x * 128 + wi * 16;
    int j0  = blockIdx.y * 64;

    float d[8][4];
    #pragma unroll
    for (int nc = 0; nc < 8; nc++)
        #pragma unroll
        for (int u = 0; u < 4; u++) d[nc][u] = 0.f;

    #pragma unroll
    for (int ks = 0; ks < 4; ks++) {
        int kp = ks * 8 + tig;
        unsigned a0 = g_phiQh2[(ib + g)     * 32 + kp];
        unsigned a1 = g_phiQh2[(ib + g + 8) * 32 + kp];
        unsigned a2 = g_phiQh2[(ib + g)     * 32 + kp + 4];
        unsigned a3 = g_phiQh2[(ib + g + 8) * 32 + kp + 4];
        #pragma unroll
        for (int nc = 0; nc < 8; nc++) {
            int jn = j0 + nc * 8 + g;
            unsigned b0 = g_phiKh2[jn * 32 + kp];
            unsigned b1 = g_phiKh2[jn * 32 + kp + 4];
            asm volatile(
                "mma.sync.aligned.m16n8k16.row.col.f32.bf16.bf16.f32 "
                "{%0,%1,%2,%3}, {%4,%5,%6,%7}, {%8,%9}, {%0,%1,%2,%3};"
                : "+f"(d[nc][0]), "+f"(d[nc][1]), "+f"(d[nc][2]), "+f"(d[nc][3])
                : "r"(a0), "r"(a1), "r"(a2), "r"(a3), "r"(b0), "r"(b1));
        }
    }

    #pragma unroll
    for (int nc = 0; nc < 8; nc++) {
        int jc = j0 + nc * 8 + tig * 2;
        *(float2*)(g_P + (size_t)(ib + g)     * N_TOK + jc) = make_float2(d[nc][0], d[nc][1]);
        *(float2*)(g_P + (size_t)(ib + g + 8) * N_TOK + jc) = make_float2(d[nc][2], d[nc][3]);
    }
}

// ---------------------------------------------------------------------
// K2: M = phi_K^T @ V   [64 x 32]. One block per r.
// ---------------------------------------------------------------------
__global__ void k2_kv()
{
    int r = blockIdx.x;
    int tid = threadIdx.x, lane = tid & 31, w = tid >> 5;

    float acc[DIM];
    #pragma unroll
    for (int c = 0; c < DIM; c++) acc[c] = 0.f;

    for (int n = tid; n < N_TOK; n += 256) {
        float pk = g_phiK[n * RFEAT + r];
        const float4* v4 = reinterpret_cast<const float4*>(g_V + n * DIM);
        #pragma unroll
        for (int c4 = 0; c4 < DIM / 4; c4++) {
            float4 t = v4[c4];
            acc[c4 * 4 + 0] = fmaf(pk, t.x, acc[c4 * 4 + 0]);
            acc[c4 * 4 + 1] = fmaf(pk, t.y, acc[c4 * 4 + 1]);
            acc[c4 * 4 + 2] = fmaf(pk, t.z, acc[c4 * 4 + 2]);
            acc[c4 * 4 + 3] = fmaf(pk, t.w, acc[c4 * 4 + 3]);
        }
    }

    __shared__ float sm[8][DIM];
    float mine = 0.f;
    #pragma unroll
    for (int c = 0; c < DIM; c++) {
        float s = warp_sum(acc[c]);
        if (lane == c) mine = s;
    }
    sm[w][lane] = mine;
    __syncthreads();
    if (tid < DIM) {
        float t = 0.f;
        #pragma unroll
        for (int ww = 0; ww < 8; ww++) t += sm[ww][tid];
        g_M[r * DIM + tid] = t;
    }
}

// ---------------------------------------------------------------------
// K3: attention + fused epilogue. 1024 threads, 16 rows/block,
// warp pair per row. exp path: fp16x2 dual-ex2 (half the MUFU ops).
// Dynamic smem (byte offsets):
//   0      sKT  [2][16][128]u32 16384  (fp16x2 k-pairs)
//   16384  sVT2 [2][32][68]u32  17408 -> 33792
//   33792  sP   [2][16][128]f32 16384 -> 50176
//   50176  sS   [16][128]f32     8192 -> 58368
//   58368  sQh  [16][16]u32      1024 -> 59392
//   60416  sPQ  [16][64]f32      4096 -> 64512
//   64512  sWo  [32][32]f32      4096 -> 68608
//   68608  sAcc [32][32]f32      4096 -> 72704
//   72704  sVec [6][32]f32        768 -> 73472
//   73472  sb1  [128]f32          512 -> 73984
//   73984  sZ1  [16][32]f32      2048 -> 76032
// Epilogue overlay in [0, 50176): sM@0, sW1@8192, sW2@24576, sH@40960.
// ---------------------------------------------------------------------
#define K3_SMEM_BYTES 76032

__device__ __forceinline__ void k3_stage(int t, int b, int tid, int i0, unsigned base)
{
    if (tid < 512) {
        int k2 = tid >> 5, c = tid & 31;
        CP_ASYNC16(base + (unsigned)(b * 8192 + k2 * 512 + c * 16),
                   g_KTh2 + k2 * N_TOK + t * 128 + c * 4);
        int pr = tid >> 5, pc = tid & 31;
        CP_ASYNC16(base + (unsigned)(33792 + b * 8192 + pr * 512 + pc * 16),
                   g_P + (size_t)(i0 + pr) * N_TOK + t * 128 + pc * 4);
    } else {
        int idx = tid - 512;
        int row = idx >> 4, c = idx & 15;
        CP_ASYNC16(base + (unsigned)(16384 + b * 8704 + row * 272 + c * 16),
                   g_VT2 + row * (N_TOK / 2) + t * 64 + c * 4);
    }
}

__global__ void __launch_bounds__(1024, 1) k3_attn(
    const int* __restrict__ mask,
    const float* __restrict__ Wo, const float* __restrict__ bo,
    const float* __restrict__ Z,
    const float* __restrict__ W1, const float* __restrict__ b1,
    const float* __restrict__ W2, const float* __restrict__ b2,
    const float* __restrict__ g1, const float* __restrict__ be1,
    const float* __restrict__ g2, const float* __restrict__ be2,
    float* __restrict__ out)
{
    extern __shared__ char sm_raw[];
    unsigned smem_base = (unsigned)__cvta_generic_to_shared(sm_raw);
    float*    sS   = (float*)(sm_raw + 50176);
    unsigned* sQh  = (unsigned*)(sm_raw + 58368);
    float*    sPQ  = (float*)(sm_raw + 60416);
    float*    sWo  = (float*)(sm_raw + 64512);
    float*    sAcc = (float*)(sm_raw + 68608);
    float*    sVec = (float*)(sm_raw + 72704);
    float*    sb1  = (float*)(sm_raw + 73472);
    float*    sZ1  = (float*)(sm_raw + 73984);
    // epilogue overlay
    float* sM   = (float*)(sm_raw);
    float* sW1  = (float*)(sm_raw + 8192);
    float* sW2  = (float*)(sm_raw + 24576);
    float* sH   = (float*)(sm_raw + 40960);

    int tid = threadIdx.x, lane = tid & 31, w = tid >> 5;
    int r16 = w >> 1, h = w & 1;
    int i0 = blockIdx.x * 16;
    int i  = i0 + r16;

    // stage persistent data
    if (tid < 256) sQh[tid] = g_Qh2[i0 * (DIM / 2) + tid];
    sPQ[tid] = g_phiQ[i0 * RFEAT + tid];
    for (int idx = tid; idx < DIM * DIM; idx += 1024) sWo[idx] = Wo[idx];
    if (tid < HDIM) sb1[tid] = b1[tid];
    if (tid < DIM) {
        sVec[tid] = bo[tid];        sVec[32 + tid] = b2[tid];
        sVec[64 + tid] = g1[tid];   sVec[96 + tid] = be1[tid];
        sVec[128 + tid] = g2[tid];  sVec[160 + tid] = be2[tid];
    }

    const int2* mrow2 = (const int2*)(mask + (size_t)i * N_TOK);
    float acc = 0.f;

    k3_stage(0, 0, tid, i0, smem_base);
    CP_COMMIT();

    for (int t = 0; t < NSUP; t++) {
        CP_WAIT0();
        __syncthreads();
        if (t + 1 < NSUP) { k3_stage(t + 1, (t + 1) & 1, tid, i0, smem_base); CP_COMMIT(); }

        int b = t & 1;
        const unsigned* KT = (const unsigned*)(sm_raw + b * 8192);
        const unsigned* VT = (const unsigned*)(sm_raw + 16384 + b * 8704) + lane * 68 + h * 32;
        int jb = h * 64 + 2 * lane;
        float2 Pw = *(const float2*)(sm_raw + 33792 + b * 8192 + r16 * 512 + jb * 4);
        int2 mv = mrow2[t * 64 + h * 32 + lane];

        // ---- exp part: fp16x2 dual-ex2, 4 split accumulator chains ----
        const __half2* qh = (const __half2*)(sQh + r16 * 16);
        __half2 aA0 = __floats2half2_rn(0.f, 0.f);
        __half2 aA1 = aA0, aB0 = aA0, aB1 = aA0;
        #pragma unroll
        for (int k2 = 0; k2 < 16; k2 += 2) {
            __half2 q0 = qh[k2], q1 = qh[k2 + 1];
            uint2 kkA = *(const uint2*)(KT + k2 * 128 + jb);
            uint2 kkB = *(const uint2*)(KT + (k2 + 1) * 128 + jb);
            aA0 = __hadd2(aA0, h2ex2(__hmul2(q0, u2h(kkA.x))));
            aB0 = __hadd2(aB0, h2ex2(__hmul2(q0, u2h(kkA.y))));
            aA1 = __hadd2(aA1, h2ex2(__hmul2(q1, u2h(kkB.x))));
            aB1 = __hadd2(aB1, h2ex2(__hmul2(q1, u2h(kkB.y))));
        }
        float eA = (__low2float(aA0) + __high2float(aA0)) + (__low2float(aA1) + __high2float(aA1));
        float eB = (__low2float(aB0) + __high2float(aB0)) + (__low2float(aB1) + __high2float(aB1));

        float2 sv;
        sv.x = (mv.x == 0) ? (eA - Pw.x) : 0.f;
        sv.y = (mv.y == 0) ? (eB - Pw.y) : 0.f;
        *(float2*)&sS[r16 * 128 + jb] = sv;
        __syncwarp();

        // ---- AV over own 64-j half: lane = output column c ----
        const float4* SS = (const float4*)&sS[r16 * 128 + h * 64];
        #pragma unroll
        for (int j8 = 0; j8 < 8; j8++) {
            uint4 v = *(const uint4*)(VT + j8 * 4);
            float4 s0 = SS[2 * j8], s1 = SS[2 * j8 + 1];
            acc = fmaf(s0.x, BFLO(v.x), acc); acc = fmaf(s0.y, BFHI(v.x), acc);
            acc = fmaf(s0.z, BFLO(v.y), acc); acc = fmaf(s0.w, BFHI(v.y), acc);
            acc = fmaf(s1.x, BFLO(v.z), acc); acc = fmaf(s1.y, BFHI(v.z), acc);
            acc = fmaf(s1.z, BFLO(v.w), acc); acc = fmaf(s1.w, BFHI(v.w), acc);
        }
        __syncwarp();
    }

    // ---- epilogue ----
    __syncthreads();
    for (int idx = tid; idx < RFEAT * DIM; idx += 1024) sM[idx] = g_M[idx];
    for (int idx = tid; idx < DIM * HDIM; idx += 1024) { sW1[idx] = W1[idx]; sW2[idx] = W2[idx]; }
    sAcc[w * 32 + lane] = acc;
    __syncthreads();

    if (h == 0) {
        float lr = 0.f;
        #pragma unroll
        for (int r = 0; r < RFEAT; r++) lr = fmaf(sPQ[r16 * RFEAT + r], sM[r * DIM + lane], lr);

        float attn = sAcc[w * 32 + lane] + sAcc[(w + 1) * 32 + lane] + lr;
        float denom = fmaxf(warp_sum(attn), 1e-6f);
        float a = attn / denom;

        sAcc[w * 32 + lane] = a;
        __syncwarp();
        float o = sVec[lane];   // bo
        #pragma unroll
        for (int c = 0; c < DIM; c++) o = fmaf(sAcc[w * 32 + c], sWo[c * DIM + lane], o);

        // LN1
        float x = Z[i * DIM + lane] + o;
        float mu = warp_sum(x) * (1.f / 32.f);
        float dd = x - mu;
        float var = warp_sum(dd * dd) * (1.f / 32.f);
        float z1 = dd * rsqrtf(var + 1e-5f) * sVec[64 + lane] + sVec[96 + lane];
        sZ1[r16 * DIM + lane] = z1;
        __syncwarp();

        // FFN up + relu
        float hh[4];
        #pragma unroll
        for (int u = 0; u < 4; u++) hh[u] = sb1[lane + u * 32];
        #pragma unroll
        for (int k = 0; k < DIM; k++) {
            float zk = sZ1[r16 * DIM + k];
            #pragma unroll
            for (int u = 0; u < 4; u++) hh[u] = fmaf(zk, sW1[k * HDIM + lane + u * 32], hh[u]);
        }
        #pragma unroll
        for (int u = 0; u < 4; u++) sH[r16 * HDIM + lane + u * 32] = fmaxf(hh[u], 0.f);
        __syncwarp();

        // FFN down
        float o0 = sVec[32 + lane], o1 = 0.f, o2 = 0.f, o3 = 0.f;
        #pragma unroll
        for (int j = 0; j < HDIM; j += 4) {
            o0 = fmaf(sH[r16 * HDIM + j + 0], sW2[(j + 0) * DIM + lane], o0);
            o1 = fmaf(sH[r16 * HDIM + j + 1], sW2[(j + 1) * DIM + lane], o1);
            o2 = fmaf(sH[r16 * HDIM + j + 2], sW2[(j + 2) * DIM + lane], o2);
            o3 = fmaf(sH[r16 * HDIM + j + 3], sW2[(j + 3) * DIM + lane], o3);
        }
        float y = z1 + ((o0 + o1) + (o2 + o3));

        // LN2
        float mu2 = warp_sum(y) * (1.f / 32.f);
        float dd2 = y - mu2;
        float var2 = warp_sum(dd2 * dd2) * (1.f / 32.f);
        out[i * DIM + lane] = dd2 * rsqrtf(var2 + 1e-5f) * sVec[128 + lane] + sVec[160 + lane];
    }
}

// ---------------------------------------------------------------------
extern "C" void kernel_launch(void* const* d_in, const int* in_sizes, int n_in,
                              void* d_out, int out_size)
{
    const float* Z    = (const float*)d_in[0];
    const int*   mask = (const int*)  d_in[1];
    const float* Wq = (const float*)d_in[2],  *bq = (const float*)d_in[3];
    const float* Wk = (const float*)d_in[4],  *bk = (const float*)d_in[5];
    const float* Wv = (const float*)d_in[6],  *bv = (const float*)d_in[7];
    const float* Wo = (const float*)d_in[8],  *bo = (const float*)d_in[9];
    const float* W1 = (const float*)d_in[10], *b1 = (const float*)d_in[11];
    const float* W2 = (const float*)d_in[12], *b2 = (const float*)d_in[13];
    const float* g1 = (const float*)d_in[14], *be1 = (const float*)d_in[15];
    const float* g2 = (const float*)d_in[16], *be2 = (const float*)d_in[17];
    const float* omega = (const float*)d_in[18];

    cudaFuncSetAttribute(k3_attn, cudaFuncAttributeMaxDynamicSharedMemorySize, K3_SMEM_BYTES);

    k1_proj<<<N_TOK / 16, 512>>>(Z, Wq, bq, Wk, bk, Wv, bv, omega);
    kP_phigemm<<<dim3(N_TOK / 128, N_TOK / 64), 256>>>();
    k2_kv<<<RFEAT, 256>>>();
    k3_attn<<<N_TOK / 16, 1024, K3_SMEM_BYTES>>>(mask, Wo, bo, Z,
                                                 W1, b1, W2, b2,
                                                 g1, be1, g2, be2, (float*)d_out);
}

// round 11
// speedup vs baseline: 1.2920x; 1.1139x over previous
#include <cuda_runtime.h>
#include <cuda_bf16.h>
#include <cuda_fp16.h>
#include <cstdint>

#define N_TOK 2048
#define DIM   32
#define RFEAT 64
#define HDIM  128
#define NSUP  (N_TOK / 128)     // 16 supertiles of 128 j

// ---------- scratch (device globals; no allocation allowed) ----------
__device__ __align__(16) float    g_V[N_TOK * DIM];
__device__ __align__(16) float    g_phiQ[N_TOK * RFEAT];
__device__ __align__(16) float    g_phiK[N_TOK * RFEAT];         // fp32, for k2
__device__ __align__(16) unsigned g_phiQh2[N_TOK * (RFEAT / 2)]; // row-major bf16x2 r-pairs
__device__ __align__(16) unsigned g_phiKh2[N_TOK * (RFEAT / 2)];
__device__ __align__(16) unsigned g_KTh2[(DIM / 2) * N_TOK];     // [k2][j] fp16x2 k-pairs (scaled K)
__device__ __align__(16) unsigned g_Qh2[N_TOK * (DIM / 2)];      // [i][k2] fp16x2 k-pairs
__device__ __align__(16) unsigned g_VT2[DIM * (N_TOK / 2)];      // [c][j2] bf16x2 j-pairs
__device__ __align__(16) float    g_M[RFEAT * DIM];              // phi_K^T @ V

__device__ __forceinline__ float fast_ex2(float x) {
    float y;
    asm("ex2.approx.ftz.f32 %0, %1;" : "=f"(y) : "f"(x));
    return y;
}
__device__ __forceinline__ __half2 h2ex2(__half2 x) {
    __half2 y;
    asm("ex2.approx.f16x2 %0, %1;" : "=r"(*(unsigned*)&y) : "r"(*(unsigned*)&x));
    return y;
}
__device__ __forceinline__ __half2 u2h(unsigned u) { return *reinterpret_cast<__half2*>(&u); }

__device__ __forceinline__ float warp_sum(float v) {
    v += __shfl_xor_sync(0xffffffffu, v, 16);
    v += __shfl_xor_sync(0xffffffffu, v, 8);
    v += __shfl_xor_sync(0xffffffffu, v, 4);
    v += __shfl_xor_sync(0xffffffffu, v, 2);
    v += __shfl_xor_sync(0xffffffffu, v, 1);
    return v;
}
__device__ __forceinline__ unsigned packbf(float a, float b) {
    __nv_bfloat162 h = __floats2bfloat162_rn(a, b);
    return *reinterpret_cast<unsigned*>(&h);
}
__device__ __forceinline__ unsigned packh(float a, float b) {
    __half2 h = __floats2half2_rn(a, b);
    return *reinterpret_cast<unsigned*>(&h);
}
#define BFLO(u) __uint_as_float((u) << 16)
#define BFHI(u) __uint_as_float((u) & 0xffff0000u)

#define CP_ASYNC16(dst_s, src_g) \
    asm volatile("cp.async.cg.shared.global [%0], [%1], 16;" :: "r"(dst_s), "l"(src_g))
#define CP_COMMIT() asm volatile("cp.async.commit_group;")
#define CP_WAIT0()  asm volatile("cp.async.wait_group 0;" ::: "memory")

#define L2E    1.4426950408889634f
#define KSCALE ((float)(1.4426950408889634 / 5.6568542494923806)) // log2e/sqrt(32)

// ---------------------------------------------------------------------
// K1: warp-per-row QKV + norms + random features.
// ---------------------------------------------------------------------
__global__ void __launch_bounds__(512) k1_proj(const float* __restrict__ Z,
                        const float* __restrict__ Wq, const float* __restrict__ bq,
                        const float* __restrict__ Wk, const float* __restrict__ bk,
                        const float* __restrict__ Wv, const float* __restrict__ bv,
                        const float* __restrict__ omega)
{
    __shared__ float sW[3][DIM * DIM];
    __shared__ float sB[3][DIM];
    __shared__ float sOm[DIM * RFEAT];
    __shared__ float sRow[16][DIM];
    __shared__ float sAn[16][DIM];
    __shared__ float sK[16][33];
    __shared__ float sVv[16][33];
    __shared__ float sQf[16][33];

    int tid = threadIdx.x, lane = tid & 31, w = tid >> 5;
    for (int idx = tid; idx < DIM * DIM; idx += 512) {
        sW[0][idx] = Wq[idx]; sW[1][idx] = Wk[idx]; sW[2][idx] = Wv[idx];
    }
    for (int idx = tid; idx < DIM * RFEAT; idx += 512) sOm[idx] = omega[idx];
    if (tid < DIM) { sB[0][tid] = bq[tid]; sB[1][tid] = bk[tid]; sB[2][tid] = bv[tid]; }

    int i0 = blockIdx.x * 16;
    int i = i0 + w;
    float zk = Z[i * DIM + lane];
    __syncthreads();

    sRow[w][lane] = zk;
    __syncwarp();

    float a[3];
    #pragma unroll
    for (int p = 0; p < 3; p++) {
        float s0 = sB[p][lane], s1 = 0.f;
        #pragma unroll
        for (int k = 0; k < DIM; k += 2) {
            s0 = fmaf(sRow[w][k],     sW[p][k * DIM + lane],       s0);
            s1 = fmaf(sRow[w][k + 1], sW[p][(k + 1) * DIM + lane], s1);
        }
        a[p] = s0 + s1;
    }
    g_V[i * DIM + lane] = a[2];
    sQf[w][lane] = a[0];
    sK[w][lane]  = a[1] * KSCALE;
    sVv[w][lane] = a[2];

    #pragma unroll
    for (int p = 0; p < 2; p++) {
        float v = a[p];
        float ss = warp_sum(v * v);
        float an = v * (1.f / fmaxf(sqrtf(ss), 1e-6f));
        sAn[w][lane] = an;
        __syncwarp();
        float d0 = 0.f, d1 = 0.f, d2 = 0.f, d3 = 0.f;
        #pragma unroll
        for (int k = 0; k < DIM; k += 2) {
            float ab0 = sAn[w][k], ab1 = sAn[w][k + 1];
            float2 om0 = *(const float2*)&sOm[k * RFEAT + 2 * lane];
            float2 om1 = *(const float2*)&sOm[(k + 1) * RFEAT + 2 * lane];
            d0 = fmaf(ab0, om0.x, d0); d1 = fmaf(ab0, om0.y, d1);
            d2 = fmaf(ab1, om1.x, d2); d3 = fmaf(ab1, om1.y, d3);
        }
        float e0 = fast_ex2((d0 + d2) * L2E) * 0.125f;  // exp(d)/sqrt(r), r=64
        float e1 = fast_ex2((d1 + d3) * L2E) * 0.125f;
        float2 ph; ph.x = e0; ph.y = e1;
        if (p == 0) {
            *(float2*)&g_phiQ[i * RFEAT + 2 * lane] = ph;
            g_phiQh2[i * (RFEAT / 2) + lane] = packbf(e0, e1);
        } else {
            *(float2*)&g_phiK[i * RFEAT + 2 * lane] = ph;
            g_phiKh2[i * (RFEAT / 2) + lane] = packbf(e0, e1);
        }
        __syncwarp();
    }

    __syncthreads();
    if (tid < 256) {
        // V^T bf16x2 j-pairs
        int k = tid >> 3, p = tid & 7;
        g_VT2[k * (N_TOK / 2) + (i0 >> 1) + p] = packbf(sVv[2 * p][k], sVv[2 * p + 1][k]);
        // K^T fp16x2 k-pairs [k2][j] and q fp16x2 k-pairs [i][k2]
        int k2 = tid >> 4, r = tid & 15;
        g_KTh2[k2 * N_TOK + i0 + r] = packh(sK[r][2 * k2], sK[r][2 * k2 + 1]);
        g_Qh2[(i0 + r) * (DIM / 2) + k2] = packh(sQf[r][2 * k2], sQf[r][2 * k2 + 1]);
    }
}

// ---------------------------------------------------------------------
// K2: M = phi_K^T @ V   [64 x 32]. One block per r.
// ---------------------------------------------------------------------
__global__ void k2_kv()
{
    int r = blockIdx.x;
    int tid = threadIdx.x, lane = tid & 31, w = tid >> 5;

    float acc[DIM];
    #pragma unroll
    for (int c = 0; c < DIM; c++) acc[c] = 0.f;

    for (int n = tid; n < N_TOK; n += 256) {
        float pk = g_phiK[n * RFEAT + r];
        const float4* v4 = reinterpret_cast<const float4*>(g_V + n * DIM);
        #pragma unroll
        for (int c4 = 0; c4 < DIM / 4; c4++) {
            float4 t = v4[c4];
            acc[c4 * 4 + 0] = fmaf(pk, t.x, acc[c4 * 4 + 0]);
            acc[c4 * 4 + 1] = fmaf(pk, t.y, acc[c4 * 4 + 1]);
            acc[c4 * 4 + 2] = fmaf(pk, t.z, acc[c4 * 4 + 2]);
            acc[c4 * 4 + 3] = fmaf(pk, t.w, acc[c4 * 4 + 3]);
        }
    }

    __shared__ float sm[8][DIM];
    float mine = 0.f;
    #pragma unroll
    for (int c = 0; c < DIM; c++) {
        float s = warp_sum(acc[c]);
        if (lane == c) mine = s;
    }
    sm[w][lane] = mine;
    __syncthreads();
    if (tid < DIM) {
        float t = 0.f;
        #pragma unroll
        for (int ww = 0; ww < 8; ww++) t += sm[ww][tid];
        g_M[r * DIM + tid] = t;
    }
}

// ---------------------------------------------------------------------
// K3: attention with FUSED phi-GEMM (mma.sync, pipelined 1 supertile
// ahead into double-buffered sP) + fused Wo/LN1/FFN/LN2 epilogue.
// 1024 threads, 16 rows/block, warp pair per row.
// Dynamic smem (byte offsets):
//   0      sKT  [2][16][128]u32 16384   (fp16x2 k-pairs)
//   16384  sVT2 [2][32][68]u32  17408 -> 33792
//   33792  sP   [2][16][128]f32 16384 -> 50176  (mma output)
//   50176  sS   [16][128]f32     8192 -> 58368
//   58368  sPQ  [16][64]f32      4096 -> 62464
//   62464  sWo  [32][32]f32      4096 -> 66560
//   66560  sAcc [32][32]f32      4096 -> 70656
//   70656  sVec [6][32]f32        768 -> 71424
//   71424  sb1  [128]f32          512 -> 71936
//   71936  sZ1  [16][32]f32      2048 -> 73984
// Epilogue overlay in [0, 50176): sM@0, sW1@8192, sW2@24576, sH@40960.
// ---------------------------------------------------------------------
#define K3_SMEM_BYTES 73984

__device__ __forceinline__ void k3_stage(int t, int b, int tid, unsigned base)
{
    if (tid < 512) {
        int k2 = tid >> 5, c = tid & 31;
        CP_ASYNC16(base + (unsigned)(b * 8192 + k2 * 512 + c * 16),
                   g_KTh2 + k2 * N_TOK + t * 128 + c * 4);
    } else {
        int idx = tid - 512;
        int row = idx >> 4, c = idx & 15;
        CP_ASYNC16(base + (unsigned)(16384 + b * 8704 + row * 272 + c * 16),
                   g_VT2 + row * (N_TOK / 2) + t * 64 + c * 4);
    }
}

__global__ void __launch_bounds__(1024, 1) k3_attn(
    const int* __restrict__ mask,
    const float* __restrict__ Wo, const float* __restrict__ bo,
    const float* __restrict__ Z,
    const float* __restrict__ W1, const float* __restrict__ b1,
    const float* __restrict__ W2, const float* __restrict__ b2,
    const float* __restrict__ g1, const float* __restrict__ be1,
    const float* __restrict__ g2, const float* __restrict__ be2,
    float* __restrict__ out)
{
    extern __shared__ char sm_raw[];
    unsigned smem_base = (unsigned)__cvta_generic_to_shared(sm_raw);
    float* sP   = (float*)(sm_raw + 33792);
    float* sS   = (float*)(sm_raw + 50176);
    float* sPQ  = (float*)(sm_raw + 58368);
    float* sWo  = (float*)(sm_raw + 62464);
    float* sAcc = (float*)(sm_raw + 66560);
    float* sVec = (float*)(sm_raw + 70656);
    float* sb1  = (float*)(sm_raw + 71424);
    float* sZ1  = (float*)(sm_raw + 71936);
    // epilogue overlay
    float* sM   = (float*)(sm_raw);
    float* sW1  = (float*)(sm_raw + 8192);
    float* sW2  = (float*)(sm_raw + 24576);
    float* sH   = (float*)(sm_raw + 40960);

    int tid = threadIdx.x, lane = tid & 31, w = tid >> 5;
    int r16 = w >> 1, h = w & 1;
    int g   = lane >> 2, tig = lane & 3;       // mma fragment coords
    int i0 = blockIdx.x * 16;
    int i  = i0 + r16;

    // stage persistent data
    sPQ[tid & 1023] = g_phiQ[i0 * RFEAT + (tid & 1023)];
    for (int idx = tid; idx < DIM * DIM; idx += 1024) sWo[idx] = Wo[idx];
    if (tid < HDIM) sb1[tid] = b1[tid];
    if (tid < DIM) {
        sVec[tid] = bo[tid];        sVec[32 + tid] = b2[tid];
        sVec[64 + tid] = g1[tid];   sVec[96 + tid] = be1[tid];
        sVec[128 + tid] = g2[tid];  sVec[160 + tid] = be2[tid];
    }

    // q fp16x2 k-pairs: loop-invariant registers (LDG broadcast per warp-pair)
    __half2 qreg[16];
    {
        const uint4* qp = (const uint4*)(g_Qh2 + i * (DIM / 2));
        #pragma unroll
        for (int u = 0; u < 4; u++) {
            uint4 t4 = qp[u];
            qreg[u * 4 + 0] = u2h(t4.x); qreg[u * 4 + 1] = u2h(t4.y);
            qreg[u * 4 + 2] = u2h(t4.z); qreg[u * 4 + 3] = u2h(t4.w);
        }
    }

    // A-fragments (phiQ, rows i0..i0+15): loop-invariant (warps 0-15 only)
    unsigned afrag[16];
    if (w < 16) {
        #pragma unroll
        for (int ks = 0; ks < 4; ks++) {
            int kp = ks * 8 + tig;
            afrag[ks * 4 + 0] = g_phiQh2[(i0 + g)     * 32 + kp];
            afrag[ks * 4 + 1] = g_phiQh2[(i0 + g + 8) * 32 + kp];
            afrag[ks * 4 + 2] = g_phiQh2[(i0 + g)     * 32 + kp + 4];
            afrag[ks * 4 + 3] = g_phiQh2[(i0 + g + 8) * 32 + kp + 4];
        }
    }

    const int2* mrow2 = (const int2*)(mask + (size_t)i * N_TOK);
    float acc = 0.f;

    k3_stage(0, 0, tid, smem_base);
    CP_COMMIT();

    // prologue: compute P for supertile 0 into sP buffer 0
    if (w < 16) {
        int jn0 = w * 8;
        float d0 = 0.f, d1 = 0.f, d2 = 0.f, d3 = 0.f;
        #pragma unroll
        for (int ks = 0; ks < 4; ks++) {
            int kp = ks * 8 + tig;
            unsigned b0 = g_phiKh2[(jn0 + g) * 32 + kp];
            unsigned b1 = g_phiKh2[(jn0 + g) * 32 + kp + 4];
            asm volatile(
                "mma.sync.aligned.m16n8k16.row.col.f32.bf16.bf16.f32 "
                "{%0,%1,%2,%3}, {%4,%5,%6,%7}, {%8,%9}, {%0,%1,%2,%3};"
                : "+f"(d0), "+f"(d1), "+f"(d2), "+f"(d3)
                : "r"(afrag[ks*4+0]), "r"(afrag[ks*4+1]),
                  "r"(afrag[ks*4+2]), "r"(afrag[ks*4+3]), "r"(b0), "r"(b1));
        }
        int jc = w * 8 + 2 * tig;
        *(float2*)&sP[g * 128 + jc]       = make_float2(d0, d1);
        *(float2*)&sP[(g + 8) * 128 + jc] = make_float2(d2, d3);
    }

    for (int t = 0; t < NSUP; t++) {
        CP_WAIT0();
        __syncthreads();       // tiles(t) + sP buf(t&1) ready; sP buf((t+1)&1) free
        if (t + 1 < NSUP) { k3_stage(t + 1, (t + 1) & 1, tid, smem_base); CP_COMMIT(); }

        // pipelined mma: P for supertile t+1 into the other sP buffer
        if (w < 16 && t + 1 < NSUP) {
            int jn0 = (t + 1) * 128 + w * 8;
            float d0 = 0.f, d1 = 0.f, d2 = 0.f, d3 = 0.f;
            #pragma unroll
            for (int ks = 0; ks < 4; ks++) {
                int kp = ks * 8 + tig;
                unsigned b0 = g_phiKh2[(jn0 + g) * 32 + kp];
                unsigned b1 = g_phiKh2[(jn0 + g) * 32 + kp + 4];
                asm volatile(
                    "mma.sync.aligned.m16n8k16.row.col.f32.bf16.bf16.f32 "
                    "{%0,%1,%2,%3}, {%4,%5,%6,%7}, {%8,%9}, {%0,%1,%2,%3};"
                    : "+f"(d0), "+f"(d1), "+f"(d2), "+f"(d3)
                    : "r"(afrag[ks*4+0]), "r"(afrag[ks*4+1]),
                      "r"(afrag[ks*4+2]), "r"(afrag[ks*4+3]), "r"(b0), "r"(b1));
            }
            float* sPb = sP + ((t + 1) & 1) * 2048;
            int jc = w * 8 + 2 * tig;
            *(float2*)&sPb[g * 128 + jc]       = make_float2(d0, d1);
            *(float2*)&sPb[(g + 8) * 128 + jc] = make_float2(d2, d3);
        }

        int b = t & 1;
        const unsigned* KT = (const unsigned*)(sm_raw + b * 8192);
        const unsigned* VT = (const unsigned*)(sm_raw + 16384 + b * 8704) + lane * 68 + h * 32;
        int jb = h * 64 + 2 * lane;
        int2 mv = mrow2[t * 64 + h * 32 + lane];

        // ---- exp part: fp16x2 dual-ex2, q in registers ----
        __half2 aA0 = __floats2half2_rn(0.f, 0.f);
        __half2 aA1 = aA0, aB0 = aA0, aB1 = aA0;
        #pragma unroll
        for (int k2 = 0; k2 < 16; k2 += 2) {
            uint2 kkA = *(const uint2*)(KT + k2 * 128 + jb);
            uint2 kkB = *(const uint2*)(KT + (k2 + 1) * 128 + jb);
            aA0 = __hadd2(aA0, h2ex2(__hmul2(qreg[k2],     u2h(kkA.x))));
            aB0 = __hadd2(aB0, h2ex2(__hmul2(qreg[k2],     u2h(kkA.y))));
            aA1 = __hadd2(aA1, h2ex2(__hmul2(qreg[k2 + 1], u2h(kkB.x))));
            aB1 = __hadd2(aB1, h2ex2(__hmul2(qreg[k2 + 1], u2h(kkB.y))));
        }
        float eA = (__low2float(aA0) + __high2float(aA0)) + (__low2float(aA1) + __high2float(aA1));
        float eB = (__low2float(aB0) + __high2float(aB0)) + (__low2float(aB1) + __high2float(aB1));

        float2 Pw = *(const float2*)&sP[b * 2048 + r16 * 128 + jb];
        float2 sv;
        sv.x = (mv.x == 0) ? (eA - Pw.x) : 0.f;
        sv.y = (mv.y == 0) ? (eB - Pw.y) : 0.f;
        *(float2*)&sS[r16 * 128 + jb] = sv;
        __syncwarp();

        // ---- AV over own 64-j half: lane = output column c ----
        const float4* SS = (const float4*)&sS[r16 * 128 + h * 64];
        #pragma unroll
        for (int j8 = 0; j8 < 8; j8++) {
            uint4 v = *(const uint4*)(VT + j8 * 4);
            float4 s0 = SS[2 * j8], s1 = SS[2 * j8 + 1];
            acc = fmaf(s0.x, BFLO(v.x), acc); acc = fmaf(s0.y, BFHI(v.x), acc);
            acc = fmaf(s0.z, BFLO(v.y), acc); acc = fmaf(s0.w, BFHI(v.y), acc);
            acc = fmaf(s1.x, BFLO(v.z), acc); acc = fmaf(s1.y, BFHI(v.z), acc);
            acc = fmaf(s1.z, BFLO(v.w), acc); acc = fmaf(s1.w, BFHI(v.w), acc);
        }
        __syncwarp();
    }

    // ---- epilogue ----
    __syncthreads();
    for (int idx = tid; idx < RFEAT * DIM; idx += 1024) sM[idx] = g_M[idx];
    for (int idx = tid; idx < DIM * HDIM; idx += 1024) { sW1[idx] = W1[idx]; sW2[idx] = W2[idx]; }
    sAcc[w * 32 + lane] = acc;
    __syncthreads();

    if (h == 0) {
        float lr = 0.f;
        #pragma unroll
        for (int r = 0; r < RFEAT; r++) lr = fmaf(sPQ[r16 * RFEAT + r], sM[r * DIM + lane], lr);

        float attn = sAcc[w * 32 + lane] + sAcc[(w + 1) * 32 + lane] + lr;
        float denom = fmaxf(warp_sum(attn), 1e-6f);
        float a = attn / denom;

        sAcc[w * 32 + lane] = a;
        __syncwarp();
        float o = sVec[lane];   // bo
        #pragma unroll
        for (int c = 0; c < DIM; c++) o = fmaf(sAcc[w * 32 + c], sWo[c * DIM + lane], o);

        // LN1
        float x = Z[i * DIM + lane] + o;
        float mu = warp_sum(x) * (1.f / 32.f);
        float dd = x - mu;
        float var = warp_sum(dd * dd) * (1.f / 32.f);
        float z1 = dd * rsqrtf(var + 1e-5f) * sVec[64 + lane] + sVec[96 + lane];
        sZ1[r16 * DIM + lane] = z1;
        __syncwarp();

        // FFN up + relu
        float hh[4];
        #pragma unroll
        for (int u = 0; u < 4; u++) hh[u] = sb1[lane + u * 32];
        #pragma unroll
        for (int k = 0; k < DIM; k++) {
            float zk = sZ1[r16 * DIM + k];
            #pragma unroll
            for (int u = 0; u < 4; u++) hh[u] = fmaf(zk, sW1[k * HDIM + lane + u * 32], hh[u]);
        }
        #pragma unroll
        for (int u = 0; u < 4; u++) sH[r16 * HDIM + lane + u * 32] = fmaxf(hh[u], 0.f);
        __syncwarp();

        // FFN down
        float o0 = sVec[32 + lane], o1 = 0.f, o2 = 0.f, o3 = 0.f;
        #pragma unroll
        for (int j = 0; j < HDIM; j += 4) {
            o0 = fmaf(sH[r16 * HDIM + j + 0], sW2[(j + 0) * DIM + lane], o0);
            o1 = fmaf(sH[r16 * HDIM + j + 1], sW2[(j + 1) * DIM + lane], o1);
            o2 = fmaf(sH[r16 * HDIM + j + 2], sW2[(j + 2) * DIM + lane], o2);
            o3 = fmaf(sH[r16 * HDIM + j + 3], sW2[(j + 3) * DIM + lane], o3);
        }
        float y = z1 + ((o0 + o1) + (o2 + o3));

        // LN2
        float mu2 = warp_sum(y) * (1.f / 32.f);
        float dd2 = y - mu2;
        float var2 = warp_sum(dd2 * dd2) * (1.f / 32.f);
        out[i * DIM + lane] = dd2 * rsqrtf(var2 + 1e-5f) * sVec[128 + lane] + sVec[160 + lane];
    }
}

// ---------------------------------------------------------------------
extern "C" void kernel_launch(void* const* d_in, const int* in_sizes, int n_in,
                              void* d_out, int out_size)
{
    const float* Z    = (const float*)d_in[0];
    const int*   mask = (const int*)  d_in[1];
    const float* Wq = (const float*)d_in[2],  *bq = (const float*)d_in[3];
    const float* Wk = (const float*)d_in[4],  *bk = (const float*)d_in[5];
    const float* Wv = (const float*)d_in[6],  *bv = (const float*)d_in[7];
    const float* Wo = (const float*)d_in[8],  *bo = (const float*)d_in[9];
    const float* W1 = (const float*)d_in[10], *b1 = (const float*)d_in[11];
    const float* W2 = (const float*)d_in[12], *b2 = (const float*)d_in[13];
    const float* g1 = (const float*)d_in[14], *be1 = (const float*)d_in[15];
    const float* g2 = (const float*)d_in[16], *be2 = (const float*)d_in[17];
    const float* omega = (const float*)d_in[18];

    cudaFuncSetAttribute(k3_attn, cudaFuncAttributeMaxDynamicSharedMemorySize, K3_SMEM_BYTES);

    k1_proj<<<N_TOK / 16, 512>>>(Z, Wq, bq, Wk, bk, Wv, bv, omega);
    k2_kv<<<RFEAT, 256>>>();
    k3_attn<<<N_TOK / 16, 1024, K3_SMEM_BYTES>>>(mask, Wo, bo, Z,
                                                 W1, b1, W2, b2,
                                                 g1, be1, g2, be2, (float*)d_out);
}